// round 13
// baseline (speedup 1.0000x reference)
#include <cuda_runtime.h>
#include <cuda_fp16.h>
#include <math.h>
#include <stdint.h>

#define BATCH   64
#define HID     1024
#define EMB     512
#define VOCAB   32000
#define G4      4096
#define M_ROWS  4032
#define NCHUNK  125
#define NBLK    128

#define SCALE_A 256.0f
#define SCALE_B 1024.0f
#define INV_SCALE (1.0f / (256.0f * 1024.0f))
#define SWZ(x) ((x) ^ (((x) >> 3) & 0x70))
#define HB_STEP_BYTES  262144
#define HB_CHUNK_BYTES 16384
#define W4_PER_BLK 64000      // float4 elements of W_out per LSTM block
#define W4_PER_STEP 1016      // per step (63*1016 >= 64000)

__device__ __align__(16) float  g_pre  [M_ROWS * G4];
__device__ __half g_Xh   [M_ROWS * EMB];
__device__ __half g_Xl   [M_ROWS * EMB];
__device__ __half g_Wih_h[G4 * EMB];
__device__ __half g_Wih_l[G4 * EMB];
__device__ __align__(16) __half g_Hb  [63 * 131072];
__device__ __align__(16) __half g_H0b [131072];
__device__ __half g_Whh_h[G4 * HID];
__device__ __half g_Whh_l[G4 * HID];
__device__ __align__(16) __half g_Bb  [(size_t)125 * 16 * 32768];
__device__ float  g_pmax [M_ROWS * NCHUNK];
__device__ int    g_parg [M_ROWS * NCHUNK];
__device__ float  g_psum [M_ROWS * NCHUNK];
__device__ float  g_plab [M_ROWS * NCHUNK];
__device__ float  g_nll  [M_ROWS];
__device__ unsigned g_bar;

__device__ __forceinline__ void cp16(void* dst, const void* src) {
    uint32_t d = (uint32_t)__cvta_generic_to_shared(dst);
    asm volatile("cp.async.cg.shared.global [%0], [%1], 16;\n" :: "r"(d), "l"(src));
}
__device__ __forceinline__ void cp_commit() { asm volatile("cp.async.commit_group;\n"); }
template <int N>
__device__ __forceinline__ void cp_wait() {
    asm volatile("cp.async.wait_group %0;\n" :: "n"(N));
}
__device__ __forceinline__ void bulkcp(uint32_t dst_smem, const void* src,
                                       uint32_t bytes, uint32_t mbar) {
    asm volatile(
        "cp.async.bulk.shared::cluster.global.mbarrier::complete_tx::bytes [%0], [%1], %2, [%3];"
        :: "r"(dst_smem), "l"(src), "r"(bytes), "r"(mbar) : "memory");
}
#define MBAR_INIT(mb, cnt) \
    asm volatile("mbarrier.init.shared.b64 [%0], %1;" :: "r"(mb), "r"((uint32_t)(cnt)) : "memory")
#define MBAR_EXPECT(mb, n) \
    asm volatile("mbarrier.arrive.expect_tx.shared.b64 _, [%0], %1;" :: "r"(mb), "r"((uint32_t)(n)) : "memory")
#define MBAR_ARRIVE(mb) \
    asm volatile("mbarrier.arrive.shared.b64 _, [%0];" :: "r"(mb) : "memory")
#define MBAR_WAIT(mb, par) do { \
    asm volatile( \
        "{\n\t.reg .pred P1;\n\t" \
        "WAIT_LOOP_%=:\n\t" \
        "mbarrier.try_wait.parity.acquire.cta.shared::cta.b64 P1, [%0], %1, 0x989680;\n\t" \
        "@P1 bra.uni WAIT_DONE_%=;\n\t" \
        "bra.uni WAIT_LOOP_%=;\n\t" \
        "WAIT_DONE_%=:\n\t}" \
        :: "r"(mb), "r"((uint32_t)(par)) : "memory"); \
} while (0)

__device__ __forceinline__ void ldm4(uint32_t& r0, uint32_t& r1, uint32_t& r2, uint32_t& r3,
                                     const void* p) {
    uint32_t a = (uint32_t)__cvta_generic_to_shared(p);
    asm volatile("ldmatrix.sync.aligned.m8n8.x4.shared.b16 {%0,%1,%2,%3}, [%4];\n"
                 : "=r"(r0), "=r"(r1), "=r"(r2), "=r"(r3) : "r"(a));
}
__device__ __forceinline__ void ldm4s(uint32_t& r0, uint32_t& r1, uint32_t& r2, uint32_t& r3,
                                      uint32_t a) {
    asm volatile("ldmatrix.sync.aligned.m8n8.x4.shared.b16 {%0,%1,%2,%3}, [%4];\n"
                 : "=r"(r0), "=r"(r1), "=r"(r2), "=r"(r3) : "r"(a));
}
__device__ __forceinline__ void mma16816(float* c, const uint32_t* a, const uint32_t* b) {
    asm volatile("mma.sync.aligned.m16n8k16.row.col.f32.f16.f16.f32 "
                 "{%0,%1,%2,%3}, {%4,%5,%6,%7}, {%8,%9}, {%0,%1,%2,%3};\n"
                 : "+f"(c[0]), "+f"(c[1]), "+f"(c[2]), "+f"(c[3])
                 : "r"(a[0]), "r"(a[1]), "r"(a[2]), "r"(a[3]), "r"(b[0]), "r"(b[1]));
}

// ---- helper: split one float4 of W_out into the blocked g_Bb layout ----
__device__ __forceinline__ void wout_split_one(const float* __restrict__ Wout, size_t i4) {
    const int v = (int)(i4 >> 10), k = (int)(i4 & 1023);
    float4 w = *(const float4*)(Wout + i4);
    float a0 = w.x * SCALE_B, a1 = w.y * SCALE_B, a2 = w.z * SCALE_B, a3 = w.w * SCALE_B;
    __half h0v = __float2half_rn(a0), h1 = __float2half_rn(a1);
    __half h2 = __float2half_rn(a2), h3 = __float2half_rn(a3);
    __half hs[4] = {h0v, h1, h2, h3};
    __half ls[4] = {__float2half_rn(a0 - __half2float(h0v)),
                    __float2half_rn(a1 - __half2float(h1)),
                    __float2half_rn(a2 - __half2float(h2)),
                    __float2half_rn(a3 - __half2float(h3))};
    const int tile = v >> 8, rl = v & 255, chunk = k >> 6, kin = k & 63;
    char* blk = (char*)g_Bb + ((size_t)(tile * 16 + chunk)) * 65536;
    const uint32_t off = (uint32_t)((rl >> 6) * 8192) + SWZ((uint32_t)((rl & 63) * 128 + kin * 2));
    *(uint2*)(blk + off)         = *(uint2*)hs;
    *(uint2*)(blk + 32768 + off) = *(uint2*)ls;
}

// ---- P0: prep (barrier, h0 split, x gather+split, Wih/Whh splits) — W_out moved to LSTM
__global__ void prep_kernel(const int* __restrict__ ot, const float* __restrict__ emb,
                            const float* __restrict__ Wih, const float* __restrict__ Whh,
                            const float* __restrict__ h0) {
    const int T = blockIdx.x * blockDim.x + threadIdx.x;
    if (T == 0) g_bar = 0u;
    if (T < BATCH * HID) {
        const int b = T >> 10, col = T & 1023;
        const int c = col >> 6, inner = col & 63;
        float a = h0[T] * SCALE_A;
        __half hh = __float2half_rn(a);
        __half hl = __float2half_rn(a - __half2float(hh));
        char* base = (char*)g_H0b + (size_t)c * HB_CHUNK_BYTES;
        const uint32_t off = SWZ((uint32_t)(b * 128 + inner * 2));
        *(__half*)(base + off)        = hh;
        *(__half*)(base + 8192 + off) = hl;
    }
    if (T < M_ROWS * EMB) {
        const int m = T >> 9, e = T & 511;
        float a = emb[(long)ot[m] * EMB + e] * SCALE_A;
        __half h = __float2half_rn(a);
        g_Xh[T] = h;
        g_Xl[T] = __float2half_rn(a - __half2float(h));
    }
    if (T < G4 * EMB) {
        float a = Wih[T] * SCALE_B;
        __half h = __float2half_rn(a);
        g_Wih_h[T] = h;
        g_Wih_l[T] = __float2half_rn(a - __half2float(h));
    }
    if (T < G4 * HID) {
        float a = Whh[T] * SCALE_B;
        __half h = __float2half_rn(a);
        g_Whh_h[T] = h;
        g_Whh_l[T] = __float2half_rn(a - __half2float(h));
    }
}

// ---- K1: pre-gates GEMM (fp16 split, 3 products) -> blocked g_pre ----
#define PRE_SMEM (3 * (1536 + 1536 + 3072 + 3072) * 2)
__global__ __launch_bounds__(256, 2)
void pre_mma_kernel(const float* __restrict__ bih, const float* __restrict__ bhh) {
    extern __shared__ __align__(16) char dsm[];
    __half* As_h = (__half*)dsm;
    __half* As_l = As_h + 3 * 1536;
    __half* Bs_h = As_l + 3 * 1536;
    __half* Bs_l = Bs_h + 3 * 3072;

    const int tid  = threadIdx.x;
    const int lane = tid & 31;
    const int warp = tid >> 5;
    const int wm   = warp >> 2;
    const int wn   = warp & 3;
    const int mblk = blockIdx.x * 64;
    const int nblk = blockIdx.y * 128;

    const __half* src[3];
    __half* arrb[3];
    int off3[3], strd[3];
#pragma unroll
    for (int s = 0; s < 3; s++) {
        int c = tid + s * 256;
        if (c < 128) {
            int row = c >> 1, col = (c & 1) * 8;
            src[s] = g_Xh + (long)(mblk + row) * EMB + col;
            arrb[s] = As_h; off3[s] = row * 24 + col; strd[s] = 1536;
        } else if (c < 256) {
            int r = c - 128, row = r >> 1, col = (r & 1) * 8;
            src[s] = g_Xl + (long)(mblk + row) * EMB + col;
            arrb[s] = As_l; off3[s] = row * 24 + col; strd[s] = 1536;
        } else if (c < 512) {
            int r = c - 256, row = r >> 1, col = (r & 1) * 8;
            src[s] = g_Wih_h + (long)(nblk + row) * EMB + col;
            arrb[s] = Bs_h; off3[s] = row * 24 + col; strd[s] = 3072;
        } else {
            int r = c - 512, row = r >> 1, col = (r & 1) * 8;
            src[s] = g_Wih_l + (long)(nblk + row) * EMB + col;
            arrb[s] = Bs_l; off3[s] = row * 24 + col; strd[s] = 3072;
        }
    }

    const int q = lane >> 3, r8 = lane & 7;
    const int rowA = (q & 1) * 8 + r8;
    const int colA = (q >> 1) * 8;
    const int rowB = (q >> 1) * 8 + r8;
    const int colB = (q & 1) * 8;

    float acc[2][4][4];
#pragma unroll
    for (int i = 0; i < 2; i++)
#pragma unroll
        for (int j = 0; j < 4; j++)
#pragma unroll
            for (int k = 0; k < 4; k++) acc[i][j][k] = 0.f;

#pragma unroll
    for (int p = 0; p < 2; p++) {
#pragma unroll
        for (int s = 0; s < 3; s++)
            cp16(arrb[s] + p * strd[s] + off3[s], src[s] + p * 16);
        cp_commit();
    }

    for (int kk = 0; kk < 32; kk++) {
        if (kk < 31) cp_wait<1>(); else cp_wait<0>();
        __syncthreads();
        if (kk + 2 < 32) {
            const int stg = (kk + 2) % 3;
#pragma unroll
            for (int s = 0; s < 3; s++)
                cp16(arrb[s] + stg * strd[s] + off3[s], src[s] + (kk + 2) * 16);
            cp_commit();
        }
        const int st = kk % 3;

        uint32_t aH[2][4], aL[2][4], bH[4][2], bL[4][2];
#pragma unroll
        for (int i = 0; i < 2; i++) {
            ldm4(aH[i][0], aH[i][1], aH[i][2], aH[i][3],
                 As_h + st * 1536 + (wm * 32 + i * 16 + rowA) * 24 + colA);
            ldm4(aL[i][0], aL[i][1], aL[i][2], aL[i][3],
                 As_l + st * 1536 + (wm * 32 + i * 16 + rowA) * 24 + colA);
        }
#pragma unroll
        for (int j2 = 0; j2 < 2; j2++) {
            ldm4(bH[j2 * 2][0], bH[j2 * 2][1], bH[j2 * 2 + 1][0], bH[j2 * 2 + 1][1],
                 Bs_h + st * 3072 + (wn * 32 + j2 * 16 + rowB) * 24 + colB);
            ldm4(bL[j2 * 2][0], bL[j2 * 2][1], bL[j2 * 2 + 1][0], bL[j2 * 2 + 1][1],
                 Bs_l + st * 3072 + (wn * 32 + j2 * 16 + rowB) * 24 + colB);
        }
#pragma unroll
        for (int i = 0; i < 2; i++)
#pragma unroll
            for (int j = 0; j < 4; j++) {
                mma16816(acc[i][j], aH[i], bH[j]);
                mma16816(acc[i][j], aH[i], bL[j]);
                mma16816(acc[i][j], aL[i], bH[j]);
            }
    }

    const int groupRow = lane >> 2;
    const int colPos   = lane & 3;
#pragma unroll
    for (int j = 0; j < 4; j++) {
        const int col  = nblk + wn * 32 + j * 8 + colPos * 2;
        const int gate = col >> 10;
        const int r10  = col & 1023;
        const int blk2 = r10 >> 3;
        const int u    = r10 & 7;
        const float bb0 = bih[col] + bhh[col];
        const float bb1 = bih[col + 1] + bhh[col + 1];
#pragma unroll
        for (int i = 0; i < 2; i++) {
#pragma unroll
            for (int half = 0; half < 2; half++) {
                const int m = mblk + wm * 32 + i * 16 + groupRow + half * 8;
                const int t = m >> 6, b = m & 63;
                float2 v;
                v.x = acc[i][j][half * 2]     * INV_SCALE + bb0;
                v.y = acc[i][j][half * 2 + 1] * INV_SCALE + bb1;
                *(float2*)(g_pre + (((size_t)(t * 128 + blk2) * 64 + b) * 32 + gate * 8 + u)) = v;
            }
        }
    }
}

// ---- K2: persistent LSTM + W_out split hidden in barrier slack ----
#define LSTM_SMEM 216400
__global__ __launch_bounds__(256, 1)
void lstm_persistent_kernel(const float* __restrict__ c0, const float* __restrict__ Wout) {
    extern __shared__ __align__(16) char smem[];
    __half* Ws_h = (__half*)smem;
    __half* Ws_l = Ws_h + 32 * 1032;
    float*  Gs   = (float*)(smem + 197632);
    float*  Cs   = (float*)(smem + 206080);
    float*  Ps   = (float*)(smem + 208128);
    const uint32_t sb  = (uint32_t)__cvta_generic_to_shared(smem);
    const uint32_t HS  = sb + 132096;
    const uint32_t PSA = sb + 208128;
    const uint32_t MBF = sb + 216320;
    const uint32_t MBP = sb + 216352;
    const uint32_t MBC = sb + 216360;

    const int tid  = threadIdx.x;
    const int lane = tid & 31;
    const int warp = tid >> 5;
    const int mw   = warp & 3;
    const int nh   = warp >> 2;
    const int blk  = blockIdx.x;

    for (int c = tid; c < 8192; c += 256) {
        const int split = c >> 12;
        const int rr    = (c >> 7) & 31;
        const int seg   = c & 127;
        const long nglob = (long)((rr >> 3) * 1024 + blk * 8 + (rr & 7));
        const __half* srcp = (split ? g_Whh_l : g_Whh_h) + nglob * HID + seg * 8;
        float4 v = *(const float4*)srcp;
        *(float4*)((split ? Ws_l : Ws_h) + rr * 1032 + seg * 8) = v;
    }
    for (int cell = tid; cell < 512; cell += 256) {
        const int b = cell >> 3, u = cell & 7;
        Cs[cell] = c0[b * HID + blk * 8 + u];
    }
    if (tid == 0) {
#pragma unroll
        for (int s = 0; s < 4; s++) MBAR_INIT(MBF + s * 8, 1);
        MBAR_INIT(MBP, 1);
#pragma unroll
        for (int s = 0; s < 4; s++) MBAR_INIT(MBC + s * 8, 8);
    }
    __syncthreads();

    const int q = lane >> 3, r8 = lane & 7;
    const int rowA = (q & 1) * 8 + r8;
    const int colA = (q >> 1) * 8;
    const int rowB = (q >> 1) * 8 + r8;
    const int colB = (q & 1) * 8;
    const int groupRow = lane >> 2;
    const int colPos   = lane & 3;

    const uint32_t aRowByte = (uint32_t)((mw * 16 + rowA) * 128 + colA * 2);
    const int c2 = blk >> 3;
    const size_t w4base = (size_t)blk * W4_PER_BLK;

    for (int t = 0; t < 63; t++) {
        const char* hsrc = t ? ((const char*)g_Hb + (size_t)(t - 1) * HB_STEP_BYTES)
                             : (const char*)g_H0b;

        if (tid == 0) {
#pragma unroll
            for (int m = 0; m < 3; m++) {
                const int F = t * 4;
                if (F) MBAR_WAIT(MBC + m * 8, (F - 1) & 1);
                MBAR_EXPECT(MBF + m * 8, HB_CHUNK_BYTES);
                bulkcp(HS + m * 16384, hsrc + (size_t)m * HB_CHUNK_BYTES,
                       HB_CHUNK_BYTES, MBF + m * 8);
            }
            MBAR_EXPECT(MBP, 8192);
            bulkcp(PSA, (const char*)g_pre + ((size_t)t * 128 + blk) * 8192, 8192, MBP);
        }

        float aHH[2][4], aHL[2][4], aLH[2][4];
#pragma unroll
        for (int j = 0; j < 2; j++)
#pragma unroll
            for (int k = 0; k < 4; k++) { aHH[j][k] = 0.f; aHL[j][k] = 0.f; aLH[j][k] = 0.f; }

        for (int c = 0; c < 16; c++) {
            if (tid == 0 && c + 3 < 16) {
                const int m = c + 3;
                const int s = m & 3;
                const int F = t * 4 + (m >> 2);
                if (F) MBAR_WAIT(MBC + s * 8, (F - 1) & 1);
                MBAR_EXPECT(MBF + s * 8, HB_CHUNK_BYTES);
                bulkcp(HS + s * 16384, hsrc + (size_t)m * HB_CHUNK_BYTES,
                       HB_CHUNK_BYTES, MBF + s * 8);
            }
            MBAR_WAIT(MBF + (c & 3) * 8, (c >> 2) & 1);
            __syncwarp();
            const uint32_t hb = HS + (c & 3) * 16384;

#pragma unroll
            for (int k16 = 0; k16 < 4; k16++) {
                uint32_t aH[4], aL[4], bH[2][2], bL[2][2];
                const uint32_t aoff = SWZ(aRowByte + (uint32_t)(k16 * 32));
                ldm4s(aH[0], aH[1], aH[2], aH[3], hb + aoff);
                ldm4s(aL[0], aL[1], aL[2], aL[3], hb + 8192 + aoff);
                ldm4(bH[0][0], bH[0][1], bH[1][0], bH[1][1],
                     Ws_h + (nh * 16 + rowB) * 1032 + c * 64 + k16 * 16 + colB);
                ldm4(bL[0][0], bL[0][1], bL[1][0], bL[1][1],
                     Ws_l + (nh * 16 + rowB) * 1032 + c * 64 + k16 * 16 + colB);
#pragma unroll
                for (int j = 0; j < 2; j++) {
                    mma16816(aHH[j], aH, bH[j]);
                    mma16816(aHL[j], aH, bL[j]);
                    mma16816(aLH[j], aL, bH[j]);
                }
            }
            __syncwarp();
            if (lane == 0) MBAR_ARRIVE(MBC + (c & 3) * 8);
        }

#pragma unroll
        for (int j = 0; j < 2; j++) {
            const int col = nh * 16 + j * 8 + colPos * 2;
            Gs[(mw * 16 + groupRow) * 33 + col]         = aHH[j][0] + aHL[j][0] + aLH[j][0];
            Gs[(mw * 16 + groupRow) * 33 + col + 1]     = aHH[j][1] + aHL[j][1] + aLH[j][1];
            Gs[(mw * 16 + groupRow + 8) * 33 + col]     = aHH[j][2] + aHL[j][2] + aLH[j][2];
            Gs[(mw * 16 + groupRow + 8) * 33 + col + 1] = aHH[j][3] + aHL[j][3] + aLH[j][3];
        }
        __syncthreads();
        MBAR_WAIT(MBP, t & 1);

        char* hdst = (char*)g_Hb + (size_t)t * HB_STEP_BYTES + (size_t)c2 * HB_CHUNK_BYTES;
        for (int cell = tid; cell < 512; cell += 256) {
            const int b = cell >> 3, u = cell & 7;
            const float gi = Gs[b * 33 + u]      * INV_SCALE + Ps[b * 32 + u];
            const float gf = Gs[b * 33 + 8 + u]  * INV_SCALE + Ps[b * 32 + 8 + u];
            const float gg = Gs[b * 33 + 16 + u] * INV_SCALE + Ps[b * 32 + 16 + u];
            const float go = Gs[b * 33 + 24 + u] * INV_SCALE + Ps[b * 32 + 24 + u];

            const float i_ = 1.f / (1.f + expf(-gi));
            const float f_ = 1.f / (1.f + expf(-gf));
            const float g_ = tanhf(gg);
            const float o_ = 1.f / (1.f + expf(-go));

            const float cN = f_ * Cs[cell] + i_ * g_;
            Cs[cell] = cN;
            const float h = o_ * tanhf(cN);

            const float a = h * SCALE_A;
            const __half hh = __float2half_rn(a);
            const __half hl = __float2half_rn(a - __half2float(hh));
            const int inner = (blk & 7) * 8 + u;
            const uint32_t off = SWZ((uint32_t)(b * 128 + inner * 2));
            *(__half*)(hdst + off)        = hh;
            *(__half*)(hdst + 8192 + off) = hl;
        }

        __syncthreads();
        // arrive at grid barrier early, then hide W_out split work in the wait slack
        if (tid == 0) {
            asm volatile("fence.proxy.async;" ::: "memory");
            __threadfence();
            atomicAdd(&g_bar, 1u);
        }
        {
            const int start = t * W4_PER_STEP;
            const int end   = (start + W4_PER_STEP < W4_PER_BLK) ? start + W4_PER_STEP
                                                                 : W4_PER_BLK;
            for (int ii = start + tid; ii < end; ii += 256)
                wout_split_one(Wout, (w4base + ii) * 4);
        }
        if (tid == 0) {
            volatile unsigned* p = &g_bar;
            const unsigned target = (unsigned)(t + 1) * NBLK;
            while (*p < target) { __nanosleep(32); }
            __threadfence();
            asm volatile("fence.proxy.async;" ::: "memory");
        }
        __syncthreads();
    }
}

// ---- K3: logits GEMM 128x256, 512 thr, bulkcp producer/consumer pipeline ----
#define LOG_STG   98304
#define LOG_TAIL  196608
#define LOG_SMEM  (LOG_TAIL + 1024 + 512 + 4 * 2048 + 512 + 64)
__global__ __launch_bounds__(512, 1)
void logits_mma_kernel(const float* __restrict__ bout, const int* __restrict__ ot) {
    extern __shared__ __align__(16) char dsm[];
    const uint32_t sb = (uint32_t)__cvta_generic_to_shared(dsm);
    float* bout_s    = (float*)(dsm + LOG_TAIL);
    int*   labels_s  = (int*)(dsm + LOG_TAIL + 1024);
    float* wmax      = (float*)(dsm + LOG_TAIL + 1536);
    int*   warg      = (int*)(dsm + LOG_TAIL + 1536 + 2048);
    float* wsum      = (float*)(dsm + LOG_TAIL + 1536 + 4096);
    float* wlab      = (float*)(dsm + LOG_TAIL + 1536 + 6144);
    float* rowmax_s  = (float*)(dsm + LOG_TAIL + 1536 + 8192);
    const uint32_t MBFL = sb + LOG_TAIL + 1536 + 8192 + 512;
    const uint32_t MBCN = MBFL + 16;

    const int tid  = threadIdx.x;
    const int lane = tid & 31;
    const int warp = tid >> 5;
    const int wm   = warp >> 2;
    const int wn   = warp & 3;
    const int mblk = blockIdx.x * 128;
    const int nblk = blockIdx.y * 256;

    if (tid < 256) bout_s[tid] = bout[nblk + tid];
    if (tid < 128) labels_s[tid] = (mblk + tid < M_ROWS) ? ot[64 + mblk + tid] : -1;
    if (tid == 0) {
        MBAR_INIT(MBFL, 1);     MBAR_INIT(MBFL + 8, 1);
        MBAR_INIT(MBCN, 16);    MBAR_INIT(MBCN + 8, 16);
    }
    __syncthreads();

    int s0 = blockIdx.x * 2;     if (s0 > 62) s0 = 62;
    int s1 = blockIdx.x * 2 + 1; if (s1 > 62) s1 = 62;
    const char* a0 = (const char*)g_Hb + (size_t)s0 * HB_STEP_BYTES;
    const char* a1 = (const char*)g_Hb + (size_t)s1 * HB_STEP_BYTES;
    const char* bb = (const char*)g_Bb + (size_t)(blockIdx.y * 16) * 65536;

    if (tid == 0) {
#pragma unroll
        for (int p = 0; p < 2; p++) {
            const uint32_t stg = sb + p * LOG_STG;
            MBAR_EXPECT(MBFL + p * 8, 98304);
            bulkcp(stg,         a0 + (size_t)p * HB_CHUNK_BYTES, 16384, MBFL + p * 8);
            bulkcp(stg + 16384, a1 + (size_t)p * HB_CHUNK_BYTES, 16384, MBFL + p * 8);
            bulkcp(stg + 32768, bb + (size_t)p * 65536,          65536, MBFL + p * 8);
        }
    }

    const int q = lane >> 3, r8 = lane & 7;
    const int rowA = (q & 1) * 8 + r8;
    const int colA = (q >> 1) * 8;
    const int rowB = (q >> 1) * 8 + r8;
    const int colB = (q & 1) * 8;

    const uint32_t aStageOff  = (uint32_t)((wm >> 1) * 16384);
    const uint32_t aRowByte   = (uint32_t)(((wm & 1) * 32 + rowA) * 128 + colA * 2);
    const uint32_t bRowByteBase = (uint32_t)((wn * 64 + rowB) * 128 + colB * 2);

    float acc[2][8][4];
#pragma unroll
    for (int i = 0; i < 2; i++)
#pragma unroll
        for (int j = 0; j < 8; j++)
#pragma unroll
            for (int k = 0; k < 4; k++) acc[i][j][k] = 0.f;

    for (int c = 0; c < 16; c++) {
        MBAR_WAIT(MBFL + (c & 1) * 8, (c >> 1) & 1);
        __syncwarp();
        const uint32_t stg = sb + (c & 1) * LOG_STG;
        const uint32_t aBaseS = stg + aStageOff;
        const uint32_t bBaseS = stg + 32768;

#pragma unroll
        for (int k16 = 0; k16 < 4; k16++) {
            uint32_t aH[2][4], aL[2][4];
#pragma unroll
            for (int i = 0; i < 2; i++) {
                const uint32_t ao = SWZ(aRowByte + (uint32_t)(i * 16 * 128 + k16 * 32));
                ldm4s(aH[i][0], aH[i][1], aH[i][2], aH[i][3], aBaseS + ao);
                ldm4s(aL[i][0], aL[i][1], aL[i][2], aL[i][3], aBaseS + 8192 + ao);
            }
#pragma unroll
            for (int j2 = 0; j2 < 4; j2++) {
                uint32_t bH[2][2], bL[2][2];
                const uint32_t bo = SWZ(bRowByteBase + (uint32_t)(j2 * 16 * 128 + k16 * 32));
                ldm4s(bH[0][0], bH[0][1], bH[1][0], bH[1][1], bBaseS + bo);
                ldm4s(bL[0][0], bL[0][1], bL[1][0], bL[1][1], bBaseS + 32768 + bo);
#pragma unroll
                for (int i = 0; i < 2; i++)
#pragma unroll
                    for (int jj = 0; jj < 2; jj++) {
                        mma16816(acc[i][j2 * 2 + jj], aH[i], bH[jj]);
                        mma16816(acc[i][j2 * 2 + jj], aH[i], bL[jj]);
                        mma16816(acc[i][j2 * 2 + jj], aL[i], bH[jj]);
                    }
            }
        }
        __syncwarp();
        if (lane == 0) MBAR_ARRIVE(MBCN + (c & 1) * 8);
        if (tid == 0 && c + 2 < 16) {
            MBAR_WAIT(MBCN + (c & 1) * 8, (c >> 1) & 1);
            const uint32_t stg2 = sb + (c & 1) * LOG_STG;
            MBAR_EXPECT(MBFL + (c & 1) * 8, 98304);
            bulkcp(stg2,         a0 + (size_t)(c + 2) * HB_CHUNK_BYTES, 16384, MBFL + (c & 1) * 8);
            bulkcp(stg2 + 16384, a1 + (size_t)(c + 2) * HB_CHUNK_BYTES, 16384, MBFL + (c & 1) * 8);
            bulkcp(stg2 + 32768, bb + (size_t)(c + 2) * 65536,          65536, MBFL + (c & 1) * 8);
        }
    }

    const int groupRow = lane >> 2;
    const int colPos   = lane & 3;

#pragma unroll
    for (int i = 0; i < 2; i++) {
#pragma unroll
        for (int half = 0; half < 2; half++) {
            const int row_local = wm * 32 + i * 16 + groupRow + half * 8;
            const int lbl = labels_s[row_local];
            float mv = -1e30f; int ma = 0x7fffffff; float lv = -1e30f;
#pragma unroll
            for (int j = 0; j < 8; j++) {
#pragma unroll
                for (int kb = 0; kb < 2; kb++) {
                    const int cl = wn * 64 + j * 8 + colPos * 2 + kb;
                    const float v = acc[i][j][half * 2 + kb] * INV_SCALE + bout_s[cl];
                    const int colg = nblk + cl;
                    if (v > mv) { mv = v; ma = colg; }
                    if (colg == lbl) lv = v;
                }
            }
#pragma unroll
            for (int m = 1; m < 4; m <<= 1) {
                const float ov = __shfl_xor_sync(0xffffffffu, mv, m);
                const int   oa = __shfl_xor_sync(0xffffffffu, ma, m);
                const float ol = __shfl_xor_sync(0xffffffffu, lv, m);
                if (ov > mv || (ov == mv && oa < ma)) { mv = ov; ma = oa; }
                lv = fmaxf(lv, ol);
            }
            if (colPos == 0) {
                wmax[row_local * 4 + wn] = mv;
                warg[row_local * 4 + wn] = ma;
                wlab[row_local * 4 + wn] = lv;
            }
        }
    }
    __syncthreads();

    if (tid < 128) {
        float mv = wmax[tid * 4]; int ma = warg[tid * 4]; float lv = wlab[tid * 4];
#pragma unroll
        for (int x = 1; x < 4; x++) {
            const float v = wmax[tid * 4 + x]; const int a = warg[tid * 4 + x];
            if (v > mv || (v == mv && a < ma)) { mv = v; ma = a; }
            lv = fmaxf(lv, wlab[tid * 4 + x]);
        }
        rowmax_s[tid] = mv;
        if (mblk + tid < M_ROWS) {
            const long p = (long)(mblk + tid) * NCHUNK + blockIdx.y;
            g_pmax[p] = mv;
            g_parg[p] = ma;
            g_plab[p] = lv;
        }
    }
    __syncthreads();

#pragma unroll
    for (int i = 0; i < 2; i++) {
#pragma unroll
        for (int half = 0; half < 2; half++) {
            const int row_local = wm * 32 + i * 16 + groupRow + half * 8;
            const float rm = rowmax_s[row_local];
            float s = 0.f;
#pragma unroll
            for (int j = 0; j < 8; j++)
#pragma unroll
                for (int kb = 0; kb < 2; kb++) {
                    const int cl = wn * 64 + j * 8 + colPos * 2 + kb;
                    s += __expf(acc[i][j][half * 2 + kb] * INV_SCALE + bout_s[cl] - rm);
                }
#pragma unroll
            for (int m = 1; m < 4; m <<= 1)
                s += __shfl_xor_sync(0xffffffffu, s, m);
            if (colPos == 0) wsum[row_local * 4 + wn] = s;
        }
    }
    __syncthreads();

    if (tid < 128 && mblk + tid < M_ROWS) {
        float s = wsum[tid * 4] + wsum[tid * 4 + 1] + wsum[tid * 4 + 2] + wsum[tid * 4 + 3];
        g_psum[(long)(mblk + tid) * NCHUNK + blockIdx.y] = s;
    }
}

// ---- K4: per-row cross-chunk reduction ----
__global__ void reduce_rows_kernel(float* __restrict__ out) {
    const int m = blockIdx.x;
    const int tid = threadIdx.x;
    const long base = (long)m * NCHUNK;

    float mv = -1e30f; int ma = 0x7fffffff;
    for (int c = tid; c < NCHUNK; c += 128) {
        const float v = g_pmax[base + c];
        const int   a = g_parg[base + c];
        if (v > mv || (v == mv && a < ma)) { mv = v; ma = a; }
    }
    __shared__ float sv[128]; __shared__ int sa[128];
    sv[tid] = mv; sa[tid] = ma;
    __syncthreads();
    for (int off = 64; off > 0; off >>= 1) {
        if (tid < off) {
            const float v = sv[tid + off]; const int a = sa[tid + off];
            if (v > sv[tid] || (v == sv[tid] && a < sa[tid])) { sv[tid] = v; sa[tid] = a; }
        }
        __syncthreads();
    }
    const float gmax = sv[0];
    const int   garg = sa[0];
    __syncthreads();

    float ssum = 0.f, lab = -1e30f;
    for (int c = tid; c < NCHUNK; c += 128) {
        ssum += g_psum[base + c] * __expf(g_pmax[base + c] - gmax);
        lab = fmaxf(lab, g_plab[base + c]);
    }
    __shared__ float s2[128]; __shared__ float s3[128];
    s2[tid] = ssum; s3[tid] = lab;
    __syncthreads();
    for (int off = 64; off > 0; off >>= 1) {
        if (tid < off) {
            s2[tid] += s2[tid + off];
            s3[tid] = fmaxf(s3[tid], s3[tid + off]);
        }
        __syncthreads();
    }

    if (tid == 0) {
        const float lse = gmax + logf(s2[0]);
        g_nll[m] = lse - s3[0];
        out[65 + m] = (float)garg;
    }
}

// ---- K5: loss assembly + first result row ----
__global__ void finalize_kernel(const int* __restrict__ ot, float* __restrict__ out) {
    const int tid = threadIdx.x;
    __shared__ float ps[64];
    if (tid < 64) out[1 + tid] = 1.0f;
    if (tid < 63) {
        float s = 0.f, cnt = 0.f;
        for (int b = 0; b < 64; b++) {
            const int lbl = ot[(tid + 1) * 64 + b];
            if (lbl != 0) { s += g_nll[tid * 64 + b]; cnt += 1.f; }
        }
        ps[tid] = s / fmaxf(cnt, 1.f);
    }
    __syncthreads();
    if (tid == 0) {
        float loss = 0.f;
        for (int t = 0; t < 63; t++) loss += ps[t];
        out[0] = loss;
    }
}

// ---- entry point ----
extern "C" void kernel_launch(void* const* d_in, const int* in_sizes, int n_in,
                              void* d_out, int out_size) {
    const int*   ot   = (const int*)  d_in[0];
    const float* h0   = (const float*)d_in[3];
    const float* c0   = (const float*)d_in[4];
    const float* emb  = (const float*)d_in[5];
    const float* Wih  = (const float*)d_in[6];
    const float* Whh  = (const float*)d_in[7];
    const float* bih  = (const float*)d_in[8];
    const float* bhh  = (const float*)d_in[9];
    const float* Wout = (const float*)d_in[10];
    const float* bout = (const float*)d_in[11];
    float* out = (float*)d_out;

    cudaFuncSetAttribute(lstm_persistent_kernel,
                         cudaFuncAttributeMaxDynamicSharedMemorySize, LSTM_SMEM);
    cudaFuncSetAttribute(pre_mma_kernel,
                         cudaFuncAttributeMaxDynamicSharedMemorySize, PRE_SMEM);
    cudaFuncSetAttribute(logits_mma_kernel,
                         cudaFuncAttributeMaxDynamicSharedMemorySize, LOG_SMEM);

    prep_kernel<<<(G4 * HID) / 256, 256>>>(ot, emb, Wih, Whh, h0);
    pre_mma_kernel<<<dim3(63, 32), 256, PRE_SMEM>>>(bih, bhh);
    lstm_persistent_kernel<<<NBLK, 256, LSTM_SMEM>>>(c0, Wout);
    logits_mma_kernel<<<dim3(32, 125), 512, LOG_SMEM>>>(bout, ot);
    reduce_rows_kernel<<<4032, 128>>>(out);
    finalize_kernel<<<1, 64>>>(ot, out);
}

// round 14
// speedup vs baseline: 1.0248x; 1.0248x over previous
#include <cuda_runtime.h>
#include <cuda_fp16.h>
#include <math.h>
#include <stdint.h>

#define BATCH   64
#define HID     1024
#define EMB     512
#define VOCAB   32000
#define G4      4096
#define M_ROWS  4032
#define NCHUNK  125
#define NBLK    128

#define SCALE_A 256.0f
#define SCALE_B 1024.0f
#define INV_SCALE (1.0f / (256.0f * 1024.0f))
#define SWZ(x) ((x) ^ (((x) >> 3) & 0x70))
#define HB_STEP_BYTES  262144
#define HB_CHUNK_BYTES 16384

__device__ __align__(16) float  g_pre  [M_ROWS * G4];
__device__ __half g_Xh   [M_ROWS * EMB];
__device__ __half g_Xl   [M_ROWS * EMB];
__device__ __half g_Wih_h[G4 * EMB];
__device__ __half g_Wih_l[G4 * EMB];
__device__ __align__(16) __half g_Hb  [63 * 131072];
__device__ __align__(16) __half g_H0b [131072];
__device__ __half g_Whh_h[G4 * HID];
__device__ __half g_Whh_l[G4 * HID];
__device__ __align__(16) __half g_Bb  [(size_t)125 * 16 * 32768];
__device__ float  g_pmax [M_ROWS * NCHUNK];
__device__ int    g_parg [M_ROWS * NCHUNK];
__device__ float  g_psum [M_ROWS * NCHUNK];
__device__ float  g_plab [M_ROWS * NCHUNK];
__device__ float  g_nll  [M_ROWS];
__device__ unsigned g_bar;

__device__ __forceinline__ void cp16(void* dst, const void* src) {
    uint32_t d = (uint32_t)__cvta_generic_to_shared(dst);
    asm volatile("cp.async.cg.shared.global [%0], [%1], 16;\n" :: "r"(d), "l"(src));
}
__device__ __forceinline__ void cp_commit() { asm volatile("cp.async.commit_group;\n"); }
template <int N>
__device__ __forceinline__ void cp_wait() {
    asm volatile("cp.async.wait_group %0;\n" :: "n"(N));
}
__device__ __forceinline__ void bulkcp(uint32_t dst_smem, const void* src,
                                       uint32_t bytes, uint32_t mbar) {
    asm volatile(
        "cp.async.bulk.shared::cluster.global.mbarrier::complete_tx::bytes [%0], [%1], %2, [%3];"
        :: "r"(dst_smem), "l"(src), "r"(bytes), "r"(mbar) : "memory");
}
#define MBAR_INIT(mb, cnt) \
    asm volatile("mbarrier.init.shared.b64 [%0], %1;" :: "r"(mb), "r"((uint32_t)(cnt)) : "memory")
#define MBAR_EXPECT(mb, n) \
    asm volatile("mbarrier.arrive.expect_tx.shared.b64 _, [%0], %1;" :: "r"(mb), "r"((uint32_t)(n)) : "memory")
#define MBAR_ARRIVE(mb) \
    asm volatile("mbarrier.arrive.shared.b64 _, [%0];" :: "r"(mb) : "memory")
#define MBAR_WAIT(mb, par) do { \
    asm volatile( \
        "{\n\t.reg .pred P1;\n\t" \
        "WAIT_LOOP_%=:\n\t" \
        "mbarrier.try_wait.parity.acquire.cta.shared::cta.b64 P1, [%0], %1, 0x989680;\n\t" \
        "@P1 bra.uni WAIT_DONE_%=;\n\t" \
        "bra.uni WAIT_LOOP_%=;\n\t" \
        "WAIT_DONE_%=:\n\t}" \
        :: "r"(mb), "r"((uint32_t)(par)) : "memory"); \
} while (0)

__device__ __forceinline__ void ldm4(uint32_t& r0, uint32_t& r1, uint32_t& r2, uint32_t& r3,
                                     const void* p) {
    uint32_t a = (uint32_t)__cvta_generic_to_shared(p);
    asm volatile("ldmatrix.sync.aligned.m8n8.x4.shared.b16 {%0,%1,%2,%3}, [%4];\n"
                 : "=r"(r0), "=r"(r1), "=r"(r2), "=r"(r3) : "r"(a));
}
__device__ __forceinline__ void ldm4s(uint32_t& r0, uint32_t& r1, uint32_t& r2, uint32_t& r3,
                                      uint32_t a) {
    asm volatile("ldmatrix.sync.aligned.m8n8.x4.shared.b16 {%0,%1,%2,%3}, [%4];\n"
                 : "=r"(r0), "=r"(r1), "=r"(r2), "=r"(r3) : "r"(a));
}
__device__ __forceinline__ void mma16816(float* c, const uint32_t* a, const uint32_t* b) {
    asm volatile("mma.sync.aligned.m16n8k16.row.col.f32.f16.f16.f32 "
                 "{%0,%1,%2,%3}, {%4,%5,%6,%7}, {%8,%9}, {%0,%1,%2,%3};\n"
                 : "+f"(c[0]), "+f"(c[1]), "+f"(c[2]), "+f"(c[3])
                 : "r"(a[0]), "r"(a[1]), "r"(a[2]), "r"(a[3]), "r"(b[0]), "r"(b[1]));
}

// ---- P0: prep (barrier, h0 split, x gather+split, Wih/Whh splits) ----
__global__ void prep_kernel(const int* __restrict__ ot, const float* __restrict__ emb,
                            const float* __restrict__ Wih, const float* __restrict__ Whh,
                            const float* __restrict__ h0) {
    const int T = blockIdx.x * blockDim.x + threadIdx.x;
    if (T == 0) g_bar = 0u;
    if (T < BATCH * HID) {
        const int b = T >> 10, col = T & 1023;
        const int c = col >> 6, inner = col & 63;
        float a = h0[T] * SCALE_A;
        __half hh = __float2half_rn(a);
        __half hl = __float2half_rn(a - __half2float(hh));
        char* base = (char*)g_H0b + (size_t)c * HB_CHUNK_BYTES;
        const uint32_t off = SWZ((uint32_t)(b * 128 + inner * 2));
        *(__half*)(base + off)        = hh;
        *(__half*)(base + 8192 + off) = hl;
    }
    if (T < M_ROWS * EMB) {
        const int m = T >> 9, e = T & 511;
        float a = emb[(long)ot[m] * EMB + e] * SCALE_A;
        __half h = __float2half_rn(a);
        g_Xh[T] = h;
        g_Xl[T] = __float2half_rn(a - __half2float(h));
    }
    if (T < G4 * EMB) {
        float a = Wih[T] * SCALE_B;
        __half h = __float2half_rn(a);
        g_Wih_h[T] = h;
        g_Wih_l[T] = __float2half_rn(a - __half2float(h));
    }
    if (T < G4 * HID) {
        float a = Whh[T] * SCALE_B;
        __half h = __float2half_rn(a);
        g_Whh_h[T] = h;
        g_Whh_l[T] = __float2half_rn(a - __half2float(h));
    }
}

// ---- K1: pre-gates GEMM fused with W_out split (tail blocks) ----
// blocks [0, 2016): GEMM tiles (mtile = bx>>5, ntile = bx&31)
// blocks [2016, 2516): W_out split, 64 float4 per thread
#define PRE_SMEM (3 * (1536 + 1536 + 3072 + 3072) * 2)
#define PRE_GEMM_BLOCKS 2016
#define PRE_SPLIT_BLOCKS 500
__global__ __launch_bounds__(256, 2)
void pre_mma_kernel(const float* __restrict__ bih, const float* __restrict__ bhh,
                    const float* __restrict__ Wout) {
    extern __shared__ __align__(16) char dsm[];
    const int tid  = threadIdx.x;

    if (blockIdx.x >= PRE_GEMM_BLOCKS) {
        // ---- W_out split slice: 500 blocks x 256 thr x 64 f4 = 8.192M f4 ----
        const int sidx = blockIdx.x - PRE_GEMM_BLOCKS;
        const size_t tbase = (size_t)(sidx * 256 + tid);
        for (int it = 0; it < 64; it++) {
            const size_t i4 = (tbase + (size_t)it * 128000) * 4;
            const int v = (int)(i4 >> 10), k = (int)(i4 & 1023);
            float4 w = *(const float4*)(Wout + i4);
            float a0 = w.x * SCALE_B, a1 = w.y * SCALE_B;
            float a2 = w.z * SCALE_B, a3 = w.w * SCALE_B;
            __half h0v = __float2half_rn(a0), h1 = __float2half_rn(a1);
            __half h2 = __float2half_rn(a2), h3 = __float2half_rn(a3);
            __half hs[4] = {h0v, h1, h2, h3};
            __half ls[4] = {__float2half_rn(a0 - __half2float(h0v)),
                            __float2half_rn(a1 - __half2float(h1)),
                            __float2half_rn(a2 - __half2float(h2)),
                            __float2half_rn(a3 - __half2float(h3))};
            const int tile = v >> 8, rl = v & 255, chunk = k >> 6, kin = k & 63;
            char* blk = (char*)g_Bb + ((size_t)(tile * 16 + chunk)) * 65536;
            const uint32_t off = (uint32_t)((rl >> 6) * 8192)
                                 + SWZ((uint32_t)((rl & 63) * 128 + kin * 2));
            *(uint2*)(blk + off)         = *(uint2*)hs;
            *(uint2*)(blk + 32768 + off) = *(uint2*)ls;
        }
        return;
    }

    // ---- GEMM tile ----
    __half* As_h = (__half*)dsm;
    __half* As_l = As_h + 3 * 1536;
    __half* Bs_h = As_l + 3 * 1536;
    __half* Bs_l = Bs_h + 3 * 3072;

    const int lane = tid & 31;
    const int warp = tid >> 5;
    const int wm   = warp >> 2;
    const int wn   = warp & 3;
    const int mblk = (blockIdx.x >> 5) * 64;
    const int nblk = (blockIdx.x & 31) * 128;

    const __half* src[3];
    __half* arrb[3];
    int off3[3], strd[3];
#pragma unroll
    for (int s = 0; s < 3; s++) {
        int c = tid + s * 256;
        if (c < 128) {
            int row = c >> 1, col = (c & 1) * 8;
            src[s] = g_Xh + (long)(mblk + row) * EMB + col;
            arrb[s] = As_h; off3[s] = row * 24 + col; strd[s] = 1536;
        } else if (c < 256) {
            int r = c - 128, row = r >> 1, col = (r & 1) * 8;
            src[s] = g_Xl + (long)(mblk + row) * EMB + col;
            arrb[s] = As_l; off3[s] = row * 24 + col; strd[s] = 1536;
        } else if (c < 512) {
            int r = c - 256, row = r >> 1, col = (r & 1) * 8;
            src[s] = g_Wih_h + (long)(nblk + row) * EMB + col;
            arrb[s] = Bs_h; off3[s] = row * 24 + col; strd[s] = 3072;
        } else {
            int r = c - 512, row = r >> 1, col = (r & 1) * 8;
            src[s] = g_Wih_l + (long)(nblk + row) * EMB + col;
            arrb[s] = Bs_l; off3[s] = row * 24 + col; strd[s] = 3072;
        }
    }

    const int q = lane >> 3, r8 = lane & 7;
    const int rowA = (q & 1) * 8 + r8;
    const int colA = (q >> 1) * 8;
    const int rowB = (q >> 1) * 8 + r8;
    const int colB = (q & 1) * 8;

    float acc[2][4][4];
#pragma unroll
    for (int i = 0; i < 2; i++)
#pragma unroll
        for (int j = 0; j < 4; j++)
#pragma unroll
            for (int k = 0; k < 4; k++) acc[i][j][k] = 0.f;

#pragma unroll
    for (int p = 0; p < 2; p++) {
#pragma unroll
        for (int s = 0; s < 3; s++)
            cp16(arrb[s] + p * strd[s] + off3[s], src[s] + p * 16);
        cp_commit();
    }

    for (int kk = 0; kk < 32; kk++) {
        if (kk < 31) cp_wait<1>(); else cp_wait<0>();
        __syncthreads();
        if (kk + 2 < 32) {
            const int stg = (kk + 2) % 3;
#pragma unroll
            for (int s = 0; s < 3; s++)
                cp16(arrb[s] + stg * strd[s] + off3[s], src[s] + (kk + 2) * 16);
            cp_commit();
        }
        const int st = kk % 3;

        uint32_t aH[2][4], aL[2][4], bH[4][2], bL[4][2];
#pragma unroll
        for (int i = 0; i < 2; i++) {
            ldm4(aH[i][0], aH[i][1], aH[i][2], aH[i][3],
                 As_h + st * 1536 + (wm * 32 + i * 16 + rowA) * 24 + colA);
            ldm4(aL[i][0], aL[i][1], aL[i][2], aL[i][3],
                 As_l + st * 1536 + (wm * 32 + i * 16 + rowA) * 24 + colA);
        }
#pragma unroll
        for (int j2 = 0; j2 < 2; j2++) {
            ldm4(bH[j2 * 2][0], bH[j2 * 2][1], bH[j2 * 2 + 1][0], bH[j2 * 2 + 1][1],
                 Bs_h + st * 3072 + (wn * 32 + j2 * 16 + rowB) * 24 + colB);
            ldm4(bL[j2 * 2][0], bL[j2 * 2][1], bL[j2 * 2 + 1][0], bL[j2 * 2 + 1][1],
                 Bs_l + st * 3072 + (wn * 32 + j2 * 16 + rowB) * 24 + colB);
        }
#pragma unroll
        for (int i = 0; i < 2; i++)
#pragma unroll
            for (int j = 0; j < 4; j++) {
                mma16816(acc[i][j], aH[i], bH[j]);
                mma16816(acc[i][j], aH[i], bL[j]);
                mma16816(acc[i][j], aL[i], bH[j]);
            }
    }

    const int groupRow = lane >> 2;
    const int colPos   = lane & 3;
#pragma unroll
    for (int j = 0; j < 4; j++) {
        const int col  = nblk + wn * 32 + j * 8 + colPos * 2;
        const int gate = col >> 10;
        const int r10  = col & 1023;
        const int blk2 = r10 >> 3;
        const int u    = r10 & 7;
        const float bb0 = bih[col] + bhh[col];
        const float bb1 = bih[col + 1] + bhh[col + 1];
#pragma unroll
        for (int i = 0; i < 2; i++) {
#pragma unroll
            for (int half = 0; half < 2; half++) {
                const int m = mblk + wm * 32 + i * 16 + groupRow + half * 8;
                const int t = m >> 6, b = m & 63;
                float2 v;
                v.x = acc[i][j][half * 2]     * INV_SCALE + bb0;
                v.y = acc[i][j][half * 2 + 1] * INV_SCALE + bb1;
                *(float2*)(g_pre + (((size_t)(t * 128 + blk2) * 64 + b) * 32 + gate * 8 + u)) = v;
            }
        }
    }
}

// ---- K2: persistent LSTM (R12 exact, 8.9us/step) ----
#define LSTM_SMEM 216400
__global__ __launch_bounds__(256, 1)
void lstm_persistent_kernel(const float* __restrict__ c0) {
    extern __shared__ __align__(16) char smem[];
    __half* Ws_h = (__half*)smem;
    __half* Ws_l = Ws_h + 32 * 1032;
    float*  Gs   = (float*)(smem + 197632);
    float*  Cs   = (float*)(smem + 206080);
    float*  Ps   = (float*)(smem + 208128);
    const uint32_t sb  = (uint32_t)__cvta_generic_to_shared(smem);
    const uint32_t HS  = sb + 132096;
    const uint32_t PSA = sb + 208128;
    const uint32_t MBF = sb + 216320;
    const uint32_t MBP = sb + 216352;
    const uint32_t MBC = sb + 216360;

    const int tid  = threadIdx.x;
    const int lane = tid & 31;
    const int warp = tid >> 5;
    const int mw   = warp & 3;
    const int nh   = warp >> 2;
    const int blk  = blockIdx.x;

    for (int c = tid; c < 8192; c += 256) {
        const int split = c >> 12;
        const int rr    = (c >> 7) & 31;
        const int seg   = c & 127;
        const long nglob = (long)((rr >> 3) * 1024 + blk * 8 + (rr & 7));
        const __half* srcp = (split ? g_Whh_l : g_Whh_h) + nglob * HID + seg * 8;
        float4 v = *(const float4*)srcp;
        *(float4*)((split ? Ws_l : Ws_h) + rr * 1032 + seg * 8) = v;
    }
    for (int cell = tid; cell < 512; cell += 256) {
        const int b = cell >> 3, u = cell & 7;
        Cs[cell] = c0[b * HID + blk * 8 + u];
    }
    if (tid == 0) {
#pragma unroll
        for (int s = 0; s < 4; s++) MBAR_INIT(MBF + s * 8, 1);
        MBAR_INIT(MBP, 1);
#pragma unroll
        for (int s = 0; s < 4; s++) MBAR_INIT(MBC + s * 8, 8);
    }
    __syncthreads();

    const int q = lane >> 3, r8 = lane & 7;
    const int rowA = (q & 1) * 8 + r8;
    const int colA = (q >> 1) * 8;
    const int rowB = (q >> 1) * 8 + r8;
    const int colB = (q & 1) * 8;
    const int groupRow = lane >> 2;
    const int colPos   = lane & 3;

    const uint32_t aRowByte = (uint32_t)((mw * 16 + rowA) * 128 + colA * 2);
    const int c2 = blk >> 3;

    for (int t = 0; t < 63; t++) {
        const char* hsrc = t ? ((const char*)g_Hb + (size_t)(t - 1) * HB_STEP_BYTES)
                             : (const char*)g_H0b;

        if (tid == 0) {
#pragma unroll
            for (int m = 0; m < 3; m++) {
                const int F = t * 4;
                if (F) MBAR_WAIT(MBC + m * 8, (F - 1) & 1);
                MBAR_EXPECT(MBF + m * 8, HB_CHUNK_BYTES);
                bulkcp(HS + m * 16384, hsrc + (size_t)m * HB_CHUNK_BYTES,
                       HB_CHUNK_BYTES, MBF + m * 8);
            }
            MBAR_EXPECT(MBP, 8192);
            bulkcp(PSA, (const char*)g_pre + ((size_t)t * 128 + blk) * 8192, 8192, MBP);
        }

        float aHH[2][4], aHL[2][4], aLH[2][4];
#pragma unroll
        for (int j = 0; j < 2; j++)
#pragma unroll
            for (int k = 0; k < 4; k++) { aHH[j][k] = 0.f; aHL[j][k] = 0.f; aLH[j][k] = 0.f; }

        for (int c = 0; c < 16; c++) {
            if (tid == 0 && c + 3 < 16) {
                const int m = c + 3;
                const int s = m & 3;
                const int F = t * 4 + (m >> 2);
                if (F) MBAR_WAIT(MBC + s * 8, (F - 1) & 1);
                MBAR_EXPECT(MBF + s * 8, HB_CHUNK_BYTES);
                bulkcp(HS + s * 16384, hsrc + (size_t)m * HB_CHUNK_BYTES,
                       HB_CHUNK_BYTES, MBF + s * 8);
            }
            MBAR_WAIT(MBF + (c & 3) * 8, (c >> 2) & 1);
            __syncwarp();
            const uint32_t hb = HS + (c & 3) * 16384;

#pragma unroll
            for (int k16 = 0; k16 < 4; k16++) {
                uint32_t aH[4], aL[4], bH[2][2], bL[2][2];
                const uint32_t aoff = SWZ(aRowByte + (uint32_t)(k16 * 32));
                ldm4s(aH[0], aH[1], aH[2], aH[3], hb + aoff);
                ldm4s(aL[0], aL[1], aL[2], aL[3], hb + 8192 + aoff);
                ldm4(bH[0][0], bH[0][1], bH[1][0], bH[1][1],
                     Ws_h + (nh * 16 + rowB) * 1032 + c * 64 + k16 * 16 + colB);
                ldm4(bL[0][0], bL[0][1], bL[1][0], bL[1][1],
                     Ws_l + (nh * 16 + rowB) * 1032 + c * 64 + k16 * 16 + colB);
#pragma unroll
                for (int j = 0; j < 2; j++) {
                    mma16816(aHH[j], aH, bH[j]);
                    mma16816(aHL[j], aH, bL[j]);
                    mma16816(aLH[j], aL, bH[j]);
                }
            }
            __syncwarp();
            if (lane == 0) MBAR_ARRIVE(MBC + (c & 3) * 8);
        }

#pragma unroll
        for (int j = 0; j < 2; j++) {
            const int col = nh * 16 + j * 8 + colPos * 2;
            Gs[(mw * 16 + groupRow) * 33 + col]         = aHH[j][0] + aHL[j][0] + aLH[j][0];
            Gs[(mw * 16 + groupRow) * 33 + col + 1]     = aHH[j][1] + aHL[j][1] + aLH[j][1];
            Gs[(mw * 16 + groupRow + 8) * 33 + col]     = aHH[j][2] + aHL[j][2] + aLH[j][2];
            Gs[(mw * 16 + groupRow + 8) * 33 + col + 1] = aHH[j][3] + aHL[j][3] + aLH[j][3];
        }
        __syncthreads();
        MBAR_WAIT(MBP, t & 1);

        char* hdst = (char*)g_Hb + (size_t)t * HB_STEP_BYTES + (size_t)c2 * HB_CHUNK_BYTES;
        for (int cell = tid; cell < 512; cell += 256) {
            const int b = cell >> 3, u = cell & 7;
            const float gi = Gs[b * 33 + u]      * INV_SCALE + Ps[b * 32 + u];
            const float gf = Gs[b * 33 + 8 + u]  * INV_SCALE + Ps[b * 32 + 8 + u];
            const float gg = Gs[b * 33 + 16 + u] * INV_SCALE + Ps[b * 32 + 16 + u];
            const float go = Gs[b * 33 + 24 + u] * INV_SCALE + Ps[b * 32 + 24 + u];

            const float i_ = 1.f / (1.f + expf(-gi));
            const float f_ = 1.f / (1.f + expf(-gf));
            const float g_ = tanhf(gg);
            const float o_ = 1.f / (1.f + expf(-go));

            const float cN = f_ * Cs[cell] + i_ * g_;
            Cs[cell] = cN;
            const float h = o_ * tanhf(cN);

            const float a = h * SCALE_A;
            const __half hh = __float2half_rn(a);
            const __half hl = __float2half_rn(a - __half2float(hh));
            const int inner = (blk & 7) * 8 + u;
            const uint32_t off = SWZ((uint32_t)(b * 128 + inner * 2));
            *(__half*)(hdst + off)        = hh;
            *(__half*)(hdst + 8192 + off) = hl;
        }

        __syncthreads();
        if (tid == 0) {
            asm volatile("fence.proxy.async;" ::: "memory");
            __threadfence();
            atomicAdd(&g_bar, 1u);
            volatile unsigned* p = &g_bar;
            const unsigned target = (unsigned)(t + 1) * NBLK;
            while (*p < target) { __nanosleep(32); }
            __threadfence();
            asm volatile("fence.proxy.async;" ::: "memory");
        }
        __syncthreads();
    }
}

// ---- K3: logits GEMM 128x256, 512 thr, bulkcp producer/consumer pipeline ----
#define LOG_STG   98304
#define LOG_TAIL  196608
#define LOG_SMEM  (LOG_TAIL + 1024 + 512 + 4 * 2048 + 512 + 64)
__global__ __launch_bounds__(512, 1)
void logits_mma_kernel(const float* __restrict__ bout, const int* __restrict__ ot) {
    extern __shared__ __align__(16) char dsm[];
    const uint32_t sb = (uint32_t)__cvta_generic_to_shared(dsm);
    float* bout_s    = (float*)(dsm + LOG_TAIL);
    int*   labels_s  = (int*)(dsm + LOG_TAIL + 1024);
    float* wmax      = (float*)(dsm + LOG_TAIL + 1536);
    int*   warg      = (int*)(dsm + LOG_TAIL + 1536 + 2048);
    float* wsum      = (float*)(dsm + LOG_TAIL + 1536 + 4096);
    float* wlab      = (float*)(dsm + LOG_TAIL + 1536 + 6144);
    float* rowmax_s  = (float*)(dsm + LOG_TAIL + 1536 + 8192);
    const uint32_t MBFL = sb + LOG_TAIL + 1536 + 8192 + 512;
    const uint32_t MBCN = MBFL + 16;

    const int tid  = threadIdx.x;
    const int lane = tid & 31;
    const int warp = tid >> 5;
    const int wm   = warp >> 2;
    const int wn   = warp & 3;
    const int mblk = blockIdx.x * 128;
    const int nblk = blockIdx.y * 256;

    if (tid < 256) bout_s[tid] = bout[nblk + tid];
    if (tid < 128) labels_s[tid] = (mblk + tid < M_ROWS) ? ot[64 + mblk + tid] : -1;
    if (tid == 0) {
        MBAR_INIT(MBFL, 1);     MBAR_INIT(MBFL + 8, 1);
        MBAR_INIT(MBCN, 16);    MBAR_INIT(MBCN + 8, 16);
    }
    __syncthreads();

    int s0 = blockIdx.x * 2;     if (s0 > 62) s0 = 62;
    int s1 = blockIdx.x * 2 + 1; if (s1 > 62) s1 = 62;
    const char* a0 = (const char*)g_Hb + (size_t)s0 * HB_STEP_BYTES;
    const char* a1 = (const char*)g_Hb + (size_t)s1 * HB_STEP_BYTES;
    const char* bb = (const char*)g_Bb + (size_t)(blockIdx.y * 16) * 65536;

    if (tid == 0) {
#pragma unroll
        for (int p = 0; p < 2; p++) {
            const uint32_t stg = sb + p * LOG_STG;
            MBAR_EXPECT(MBFL + p * 8, 98304);
            bulkcp(stg,         a0 + (size_t)p * HB_CHUNK_BYTES, 16384, MBFL + p * 8);
            bulkcp(stg + 16384, a1 + (size_t)p * HB_CHUNK_BYTES, 16384, MBFL + p * 8);
            bulkcp(stg + 32768, bb + (size_t)p * 65536,          65536, MBFL + p * 8);
        }
    }

    const int q = lane >> 3, r8 = lane & 7;
    const int rowA = (q & 1) * 8 + r8;
    const int colA = (q >> 1) * 8;
    const int rowB = (q >> 1) * 8 + r8;
    const int colB = (q & 1) * 8;

    const uint32_t aStageOff  = (uint32_t)((wm >> 1) * 16384);
    const uint32_t aRowByte   = (uint32_t)(((wm & 1) * 32 + rowA) * 128 + colA * 2);
    const uint32_t bRowByteBase = (uint32_t)((wn * 64 + rowB) * 128 + colB * 2);

    float acc[2][8][4];
#pragma unroll
    for (int i = 0; i < 2; i++)
#pragma unroll
        for (int j = 0; j < 8; j++)
#pragma unroll
            for (int k = 0; k < 4; k++) acc[i][j][k] = 0.f;

    for (int c = 0; c < 16; c++) {
        MBAR_WAIT(MBFL + (c & 1) * 8, (c >> 1) & 1);
        __syncwarp();
        const uint32_t stg = sb + (c & 1) * LOG_STG;
        const uint32_t aBaseS = stg + aStageOff;
        const uint32_t bBaseS = stg + 32768;

#pragma unroll
        for (int k16 = 0; k16 < 4; k16++) {
            uint32_t aH[2][4], aL[2][4];
#pragma unroll
            for (int i = 0; i < 2; i++) {
                const uint32_t ao = SWZ(aRowByte + (uint32_t)(i * 16 * 128 + k16 * 32));
                ldm4s(aH[i][0], aH[i][1], aH[i][2], aH[i][3], aBaseS + ao);
                ldm4s(aL[i][0], aL[i][1], aL[i][2], aL[i][3], aBaseS + 8192 + ao);
            }
#pragma unroll
            for (int j2 = 0; j2 < 4; j2++) {
                uint32_t bH[2][2], bL[2][2];
                const uint32_t bo = SWZ(bRowByteBase + (uint32_t)(j2 * 16 * 128 + k16 * 32));
                ldm4s(bH[0][0], bH[0][1], bH[1][0], bH[1][1], bBaseS + bo);
                ldm4s(bL[0][0], bL[0][1], bL[1][0], bL[1][1], bBaseS + 32768 + bo);
#pragma unroll
                for (int i = 0; i < 2; i++)
#pragma unroll
                    for (int jj = 0; jj < 2; jj++) {
                        mma16816(acc[i][j2 * 2 + jj], aH[i], bH[jj]);
                        mma16816(acc[i][j2 * 2 + jj], aH[i], bL[jj]);
                        mma16816(acc[i][j2 * 2 + jj], aL[i], bH[jj]);
                    }
            }
        }
        __syncwarp();
        if (lane == 0) MBAR_ARRIVE(MBCN + (c & 1) * 8);
        if (tid == 0 && c + 2 < 16) {
            MBAR_WAIT(MBCN + (c & 1) * 8, (c >> 1) & 1);
            const uint32_t stg2 = sb + (c & 1) * LOG_STG;
            MBAR_EXPECT(MBFL + (c & 1) * 8, 98304);
            bulkcp(stg2,         a0 + (size_t)(c + 2) * HB_CHUNK_BYTES, 16384, MBFL + (c & 1) * 8);
            bulkcp(stg2 + 16384, a1 + (size_t)(c + 2) * HB_CHUNK_BYTES, 16384, MBFL + (c & 1) * 8);
            bulkcp(stg2 + 32768, bb + (size_t)(c + 2) * 65536,          65536, MBFL + (c & 1) * 8);
        }
    }

    const int groupRow = lane >> 2;
    const int colPos   = lane & 3;

#pragma unroll
    for (int i = 0; i < 2; i++) {
#pragma unroll
        for (int half = 0; half < 2; half++) {
            const int row_local = wm * 32 + i * 16 + groupRow + half * 8;
            const int lbl = labels_s[row_local];
            float mv = -1e30f; int ma = 0x7fffffff; float lv = -1e30f;
#pragma unroll
            for (int j = 0; j < 8; j++) {
#pragma unroll
                for (int kb = 0; kb < 2; kb++) {
                    const int cl = wn * 64 + j * 8 + colPos * 2 + kb;
                    const float v = acc[i][j][half * 2 + kb] * INV_SCALE + bout_s[cl];
                    const int colg = nblk + cl;
                    if (v > mv) { mv = v; ma = colg; }
                    if (colg == lbl) lv = v;
                }
            }
#pragma unroll
            for (int m = 1; m < 4; m <<= 1) {
                const float ov = __shfl_xor_sync(0xffffffffu, mv, m);
                const int   oa = __shfl_xor_sync(0xffffffffu, ma, m);
                const float ol = __shfl_xor_sync(0xffffffffu, lv, m);
                if (ov > mv || (ov == mv && oa < ma)) { mv = ov; ma = oa; }
                lv = fmaxf(lv, ol);
            }
            if (colPos == 0) {
                wmax[row_local * 4 + wn] = mv;
                warg[row_local * 4 + wn] = ma;
                wlab[row_local * 4 + wn] = lv;
            }
        }
    }
    __syncthreads();

    if (tid < 128) {
        float mv = wmax[tid * 4]; int ma = warg[tid * 4]; float lv = wlab[tid * 4];
#pragma unroll
        for (int x = 1; x < 4; x++) {
            const float v = wmax[tid * 4 + x]; const int a = warg[tid * 4 + x];
            if (v > mv || (v == mv && a < ma)) { mv = v; ma = a; }
            lv = fmaxf(lv, wlab[tid * 4 + x]);
        }
        rowmax_s[tid] = mv;
        if (mblk + tid < M_ROWS) {
            const long p = (long)(mblk + tid) * NCHUNK + blockIdx.y;
            g_pmax[p] = mv;
            g_parg[p] = ma;
            g_plab[p] = lv;
        }
    }
    __syncthreads();

#pragma unroll
    for (int i = 0; i < 2; i++) {
#pragma unroll
        for (int half = 0; half < 2; half++) {
            const int row_local = wm * 32 + i * 16 + groupRow + half * 8;
            const float rm = rowmax_s[row_local];
            float s = 0.f;
#pragma unroll
            for (int j = 0; j < 8; j++)
#pragma unroll
                for (int kb = 0; kb < 2; kb++) {
                    const int cl = wn * 64 + j * 8 + colPos * 2 + kb;
                    s += __expf(acc[i][j][half * 2 + kb] * INV_SCALE + bout_s[cl] - rm);
                }
#pragma unroll
            for (int m = 1; m < 4; m <<= 1)
                s += __shfl_xor_sync(0xffffffffu, s, m);
            if (colPos == 0) wsum[row_local * 4 + wn] = s;
        }
    }
    __syncthreads();

    if (tid < 128 && mblk + tid < M_ROWS) {
        float s = wsum[tid * 4] + wsum[tid * 4 + 1] + wsum[tid * 4 + 2] + wsum[tid * 4 + 3];
        g_psum[(long)(mblk + tid) * NCHUNK + blockIdx.y] = s;
    }
}

// ---- K4: per-row cross-chunk reduction ----
__global__ void reduce_rows_kernel(float* __restrict__ out) {
    const int m = blockIdx.x;
    const int tid = threadIdx.x;
    const long base = (long)m * NCHUNK;

    float mv = -1e30f; int ma = 0x7fffffff;
    for (int c = tid; c < NCHUNK; c += 128) {
        const float v = g_pmax[base + c];
        const int   a = g_parg[base + c];
        if (v > mv || (v == mv && a < ma)) { mv = v; ma = a; }
    }
    __shared__ float sv[128]; __shared__ int sa[128];
    sv[tid] = mv; sa[tid] = ma;
    __syncthreads();
    for (int off = 64; off > 0; off >>= 1) {
        if (tid < off) {
            const float v = sv[tid + off]; const int a = sa[tid + off];
            if (v > sv[tid] || (v == sv[tid] && a < sa[tid])) { sv[tid] = v; sa[tid] = a; }
        }
        __syncthreads();
    }
    const float gmax = sv[0];
    const int   garg = sa[0];
    __syncthreads();

    float ssum = 0.f, lab = -1e30f;
    for (int c = tid; c < NCHUNK; c += 128) {
        ssum += g_psum[base + c] * __expf(g_pmax[base + c] - gmax);
        lab = fmaxf(lab, g_plab[base + c]);
    }
    __shared__ float s2[128]; __shared__ float s3[128];
    s2[tid] = ssum; s3[tid] = lab;
    __syncthreads();
    for (int off = 64; off > 0; off >>= 1) {
        if (tid < off) {
            s2[tid] += s2[tid + off];
            s3[tid] = fmaxf(s3[tid], s3[tid + off]);
        }
        __syncthreads();
    }

    if (tid == 0) {
        const float lse = gmax + logf(s2[0]);
        g_nll[m] = lse - s3[0];
        out[65 + m] = (float)garg;
    }
}

// ---- K5: loss assembly + first result row ----
__global__ void finalize_kernel(const int* __restrict__ ot, float* __restrict__ out) {
    const int tid = threadIdx.x;
    __shared__ float ps[64];
    if (tid < 64) out[1 + tid] = 1.0f;
    if (tid < 63) {
        float s = 0.f, cnt = 0.f;
        for (int b = 0; b < 64; b++) {
            const int lbl = ot[(tid + 1) * 64 + b];
            if (lbl != 0) { s += g_nll[tid * 64 + b]; cnt += 1.f; }
        }
        ps[tid] = s / fmaxf(cnt, 1.f);
    }
    __syncthreads();
    if (tid == 0) {
        float loss = 0.f;
        for (int t = 0; t < 63; t++) loss += ps[t];
        out[0] = loss;
    }
}

// ---- entry point ----
extern "C" void kernel_launch(void* const* d_in, const int* in_sizes, int n_in,
                              void* d_out, int out_size) {
    const int*   ot   = (const int*)  d_in[0];
    const float* h0   = (const float*)d_in[3];
    const float* c0   = (const float*)d_in[4];
    const float* emb  = (const float*)d_in[5];
    const float* Wih  = (const float*)d_in[6];
    const float* Whh  = (const float*)d_in[7];
    const float* bih  = (const float*)d_in[8];
    const float* bhh  = (const float*)d_in[9];
    const float* Wout = (const float*)d_in[10];
    const float* bout = (const float*)d_in[11];
    float* out = (float*)d_out;

    cudaFuncSetAttribute(lstm_persistent_kernel,
                         cudaFuncAttributeMaxDynamicSharedMemorySize, LSTM_SMEM);
    cudaFuncSetAttribute(pre_mma_kernel,
                         cudaFuncAttributeMaxDynamicSharedMemorySize, PRE_SMEM);
    cudaFuncSetAttribute(logits_mma_kernel,
                         cudaFuncAttributeMaxDynamicSharedMemorySize, LOG_SMEM);

    prep_kernel<<<(G4 * HID) / 256, 256>>>(ot, emb, Wih, Whh, h0);
    pre_mma_kernel<<<PRE_GEMM_BLOCKS + PRE_SPLIT_BLOCKS, 256, PRE_SMEM>>>(bih, bhh, Wout);
    lstm_persistent_kernel<<<NBLK, 256, LSTM_SMEM>>>(c0);
    logits_mma_kernel<<<dim3(32, 125), 512, LOG_SMEM>>>(bout, ot);
    reduce_rows_kernel<<<4032, 128>>>(out);
    finalize_kernel<<<1, 64>>>(ot, out);
}

// round 15
// speedup vs baseline: 1.0419x; 1.0167x over previous
#include <cuda_runtime.h>
#include <cuda_fp16.h>
#include <math.h>
#include <stdint.h>

#define BATCH   64
#define HID     1024
#define EMB     512
#define VOCAB   32000
#define G4      4096
#define M_ROWS  4032
#define NCHUNK  125
#define NBLK    128

#define SCALE_A 256.0f
#define SCALE_B 1024.0f
#define INV_SCALE (1.0f / (256.0f * 1024.0f))
#define SWZ(x) ((x) ^ (((x) >> 3) & 0x70))
#define HB_STEP_BYTES  262144
#define HB_CHUNK_BYTES 16384

__device__ __align__(16) float  g_pre  [M_ROWS * G4];
__device__ __half g_Xh   [M_ROWS * EMB];
__device__ __half g_Xl   [M_ROWS * EMB];
__device__ __half g_Wih_h[G4 * EMB];
__device__ __half g_Wih_l[G4 * EMB];
__device__ __align__(16) __half g_Hb  [63 * 131072];
__device__ __align__(16) __half g_H0b [131072];
__device__ __half g_Whh_h[G4 * HID];
__device__ __half g_Whh_l[G4 * HID];
__device__ __align__(16) __half g_Bb  [(size_t)125 * 16 * 32768];
__device__ float  g_pmax [M_ROWS * NCHUNK];
__device__ int    g_parg [M_ROWS * NCHUNK];
__device__ float  g_psum [M_ROWS * NCHUNK];
__device__ float  g_plab [M_ROWS * NCHUNK];
__device__ float  g_nll  [M_ROWS];
__device__ unsigned g_bar;

__device__ __forceinline__ void cp16(void* dst, const void* src) {
    uint32_t d = (uint32_t)__cvta_generic_to_shared(dst);
    asm volatile("cp.async.cg.shared.global [%0], [%1], 16;\n" :: "r"(d), "l"(src));
}
__device__ __forceinline__ void cp_commit() { asm volatile("cp.async.commit_group;\n"); }
template <int N>
__device__ __forceinline__ void cp_wait() {
    asm volatile("cp.async.wait_group %0;\n" :: "n"(N));
}
__device__ __forceinline__ void bulkcp(uint32_t dst_smem, const void* src,
                                       uint32_t bytes, uint32_t mbar) {
    asm volatile(
        "cp.async.bulk.shared::cluster.global.mbarrier::complete_tx::bytes [%0], [%1], %2, [%3];"
        :: "r"(dst_smem), "l"(src), "r"(bytes), "r"(mbar) : "memory");
}
#define MBAR_INIT(mb, cnt) \
    asm volatile("mbarrier.init.shared.b64 [%0], %1;" :: "r"(mb), "r"((uint32_t)(cnt)) : "memory")
#define MBAR_EXPECT(mb, n) \
    asm volatile("mbarrier.arrive.expect_tx.shared.b64 _, [%0], %1;" :: "r"(mb), "r"((uint32_t)(n)) : "memory")
#define MBAR_ARRIVE(mb) \
    asm volatile("mbarrier.arrive.shared.b64 _, [%0];" :: "r"(mb) : "memory")
#define MBAR_WAIT(mb, par) do { \
    asm volatile( \
        "{\n\t.reg .pred P1;\n\t" \
        "WAIT_LOOP_%=:\n\t" \
        "mbarrier.try_wait.parity.acquire.cta.shared::cta.b64 P1, [%0], %1, 0x989680;\n\t" \
        "@P1 bra.uni WAIT_DONE_%=;\n\t" \
        "bra.uni WAIT_LOOP_%=;\n\t" \
        "WAIT_DONE_%=:\n\t}" \
        :: "r"(mb), "r"((uint32_t)(par)) : "memory"); \
} while (0)

__device__ __forceinline__ void ldm4(uint32_t& r0, uint32_t& r1, uint32_t& r2, uint32_t& r3,
                                     const void* p) {
    uint32_t a = (uint32_t)__cvta_generic_to_shared(p);
    asm volatile("ldmatrix.sync.aligned.m8n8.x4.shared.b16 {%0,%1,%2,%3}, [%4];\n"
                 : "=r"(r0), "=r"(r1), "=r"(r2), "=r"(r3) : "r"(a));
}
__device__ __forceinline__ void ldm4s(uint32_t& r0, uint32_t& r1, uint32_t& r2, uint32_t& r3,
                                      uint32_t a) {
    asm volatile("ldmatrix.sync.aligned.m8n8.x4.shared.b16 {%0,%1,%2,%3}, [%4];\n"
                 : "=r"(r0), "=r"(r1), "=r"(r2), "=r"(r3) : "r"(a));
}
__device__ __forceinline__ void mma16816(float* c, const uint32_t* a, const uint32_t* b) {
    asm volatile("mma.sync.aligned.m16n8k16.row.col.f32.f16.f16.f32 "
                 "{%0,%1,%2,%3}, {%4,%5,%6,%7}, {%8,%9}, {%0,%1,%2,%3};\n"
                 : "+f"(c[0]), "+f"(c[1]), "+f"(c[2]), "+f"(c[3])
                 : "r"(a[0]), "r"(a[1]), "r"(a[2]), "r"(a[3]), "r"(b[0]), "r"(b[1]));
}

// ---- P0: fused prep (barrier, h0 split, x gather+split, Wih/Whh splits, W_out block) --
__global__ void prep_all_kernel(const int* __restrict__ ot, const float* __restrict__ emb,
                                const float* __restrict__ Wih, const float* __restrict__ Whh,
                                const float* __restrict__ h0, const float* __restrict__ Wout) {
    const int T = blockIdx.x * blockDim.x + threadIdx.x;
    if (T == 0) g_bar = 0u;
    if (T < BATCH * HID) {
        const int b = T >> 10, col = T & 1023;
        const int c = col >> 6, inner = col & 63;
        float a = h0[T] * SCALE_A;
        __half hh = __float2half_rn(a);
        __half hl = __float2half_rn(a - __half2float(hh));
        char* base = (char*)g_H0b + (size_t)c * HB_CHUNK_BYTES;
        const uint32_t off = SWZ((uint32_t)(b * 128 + inner * 2));
        *(__half*)(base + off)        = hh;
        *(__half*)(base + 8192 + off) = hl;
    }
    if (T < M_ROWS * EMB) {
        const int m = T >> 9, e = T & 511;
        float a = emb[(long)ot[m] * EMB + e] * SCALE_A;
        __half h = __float2half_rn(a);
        g_Xh[T] = h;
        g_Xl[T] = __float2half_rn(a - __half2float(h));
    }
    if (T < G4 * EMB) {
        float a = Wih[T] * SCALE_B;
        __half h = __float2half_rn(a);
        g_Wih_h[T] = h;
        g_Wih_l[T] = __float2half_rn(a - __half2float(h));
    }
    if (T < G4 * HID) {
        float a = Whh[T] * SCALE_B;
        __half h = __float2half_rn(a);
        g_Whh_h[T] = h;
        g_Whh_l[T] = __float2half_rn(a - __half2float(h));
    }
    const size_t i4 = (size_t)T * 4;
    if (i4 < (size_t)VOCAB * HID) {
        const int v = (int)(i4 >> 10), k = (int)(i4 & 1023);
        float4 w = *(const float4*)(Wout + i4);
        float a0 = w.x * SCALE_B, a1 = w.y * SCALE_B, a2 = w.z * SCALE_B, a3 = w.w * SCALE_B;
        __half h0v = __float2half_rn(a0), h1 = __float2half_rn(a1);
        __half h2 = __float2half_rn(a2), h3 = __float2half_rn(a3);
        __half hs[4] = {h0v, h1, h2, h3};
        __half ls[4] = {__float2half_rn(a0 - __half2float(h0v)),
                        __float2half_rn(a1 - __half2float(h1)),
                        __float2half_rn(a2 - __half2float(h2)),
                        __float2half_rn(a3 - __half2float(h3))};
        const int tile = v >> 8, rl = v & 255, chunk = k >> 6, kin = k & 63;
        char* blk = (char*)g_Bb + ((size_t)(tile * 16 + chunk)) * 65536;
        const uint32_t off = (uint32_t)((rl >> 6) * 8192) + SWZ((uint32_t)((rl & 63) * 128 + kin * 2));
        *(uint2*)(blk + off)         = *(uint2*)hs;
        *(uint2*)(blk + 32768 + off) = *(uint2*)ls;
    }
}

// ---- K1: pre-gates GEMM (fp16 split, 3 products) -> blocked g_pre ----
#define PRE_SMEM (3 * (1536 + 1536 + 3072 + 3072) * 2)
__global__ __launch_bounds__(256, 2)
void pre_mma_kernel(const float* __restrict__ bih, const float* __restrict__ bhh) {
    extern __shared__ __align__(16) char dsm[];
    __half* As_h = (__half*)dsm;
    __half* As_l = As_h + 3 * 1536;
    __half* Bs_h = As_l + 3 * 1536;
    __half* Bs_l = Bs_h + 3 * 3072;

    const int tid  = threadIdx.x;
    const int lane = tid & 31;
    const int warp = tid >> 5;
    const int wm   = warp >> 2;
    const int wn   = warp & 3;
    const int mblk = blockIdx.x * 64;
    const int nblk = blockIdx.y * 128;

    const __half* src[3];
    __half* arrb[3];
    int off3[3], strd[3];
#pragma unroll
    for (int s = 0; s < 3; s++) {
        int c = tid + s * 256;
        if (c < 128) {
            int row = c >> 1, col = (c & 1) * 8;
            src[s] = g_Xh + (long)(mblk + row) * EMB + col;
            arrb[s] = As_h; off3[s] = row * 24 + col; strd[s] = 1536;
        } else if (c < 256) {
            int r = c - 128, row = r >> 1, col = (r & 1) * 8;
            src[s] = g_Xl + (long)(mblk + row) * EMB + col;
            arrb[s] = As_l; off3[s] = row * 24 + col; strd[s] = 1536;
        } else if (c < 512) {
            int r = c - 256, row = r >> 1, col = (r & 1) * 8;
            src[s] = g_Wih_h + (long)(nblk + row) * EMB + col;
            arrb[s] = Bs_h; off3[s] = row * 24 + col; strd[s] = 3072;
        } else {
            int r = c - 512, row = r >> 1, col = (r & 1) * 8;
            src[s] = g_Wih_l + (long)(nblk + row) * EMB + col;
            arrb[s] = Bs_l; off3[s] = row * 24 + col; strd[s] = 3072;
        }
    }

    const int q = lane >> 3, r8 = lane & 7;
    const int rowA = (q & 1) * 8 + r8;
    const int colA = (q >> 1) * 8;
    const int rowB = (q >> 1) * 8 + r8;
    const int colB = (q & 1) * 8;

    float acc[2][4][4];
#pragma unroll
    for (int i = 0; i < 2; i++)
#pragma unroll
        for (int j = 0; j < 4; j++)
#pragma unroll
            for (int k = 0; k < 4; k++) acc[i][j][k] = 0.f;

#pragma unroll
    for (int p = 0; p < 2; p++) {
#pragma unroll
        for (int s = 0; s < 3; s++)
            cp16(arrb[s] + p * strd[s] + off3[s], src[s] + p * 16);
        cp_commit();
    }

    for (int kk = 0; kk < 32; kk++) {
        if (kk < 31) cp_wait<1>(); else cp_wait<0>();
        __syncthreads();
        if (kk + 2 < 32) {
            const int stg = (kk + 2) % 3;
#pragma unroll
            for (int s = 0; s < 3; s++)
                cp16(arrb[s] + stg * strd[s] + off3[s], src[s] + (kk + 2) * 16);
            cp_commit();
        }
        const int st = kk % 3;

        uint32_t aH[2][4], aL[2][4], bH[4][2], bL[4][2];
#pragma unroll
        for (int i = 0; i < 2; i++) {
            ldm4(aH[i][0], aH[i][1], aH[i][2], aH[i][3],
                 As_h + st * 1536 + (wm * 32 + i * 16 + rowA) * 24 + colA);
            ldm4(aL[i][0], aL[i][1], aL[i][2], aL[i][3],
                 As_l + st * 1536 + (wm * 32 + i * 16 + rowA) * 24 + colA);
        }
#pragma unroll
        for (int j2 = 0; j2 < 2; j2++) {
            ldm4(bH[j2 * 2][0], bH[j2 * 2][1], bH[j2 * 2 + 1][0], bH[j2 * 2 + 1][1],
                 Bs_h + st * 3072 + (wn * 32 + j2 * 16 + rowB) * 24 + colB);
            ldm4(bL[j2 * 2][0], bL[j2 * 2][1], bL[j2 * 2 + 1][0], bL[j2 * 2 + 1][1],
                 Bs_l + st * 3072 + (wn * 32 + j2 * 16 + rowB) * 24 + colB);
        }
#pragma unroll
        for (int i = 0; i < 2; i++)
#pragma unroll
            for (int j = 0; j < 4; j++) {
                mma16816(acc[i][j], aH[i], bH[j]);
                mma16816(acc[i][j], aH[i], bL[j]);
                mma16816(acc[i][j], aL[i], bH[j]);
            }
    }

    const int groupRow = lane >> 2;
    const int colPos   = lane & 3;
#pragma unroll
    for (int j = 0; j < 4; j++) {
        const int col  = nblk + wn * 32 + j * 8 + colPos * 2;
        const int gate = col >> 10;
        const int r10  = col & 1023;
        const int blk2 = r10 >> 3;
        const int u    = r10 & 7;
        const float bb0 = bih[col] + bhh[col];
        const float bb1 = bih[col + 1] + bhh[col + 1];
#pragma unroll
        for (int i = 0; i < 2; i++) {
#pragma unroll
            for (int half = 0; half < 2; half++) {
                const int m = mblk + wm * 32 + i * 16 + groupRow + half * 8;
                const int t = m >> 6, b = m & 63;
                float2 v;
                v.x = acc[i][j][half * 2]     * INV_SCALE + bb0;
                v.y = acc[i][j][half * 2 + 1] * INV_SCALE + bb1;
                *(float2*)(g_pre + (((size_t)(t * 128 + blk2) * 64 + b) * 32 + gate * 8 + u)) = v;
            }
        }
    }
}

// ---- K2: persistent LSTM (passing version, 8.9us/step) ----
#define LSTM_SMEM 216400
__global__ __launch_bounds__(256, 1)
void lstm_persistent_kernel(const float* __restrict__ c0) {
    extern __shared__ __align__(16) char smem[];
    __half* Ws_h = (__half*)smem;
    __half* Ws_l = Ws_h + 32 * 1032;
    float*  Gs   = (float*)(smem + 197632);
    float*  Cs   = (float*)(smem + 206080);
    float*  Ps   = (float*)(smem + 208128);
    const uint32_t sb  = (uint32_t)__cvta_generic_to_shared(smem);
    const uint32_t HS  = sb + 132096;
    const uint32_t PSA = sb + 208128;
    const uint32_t MBF = sb + 216320;
    const uint32_t MBP = sb + 216352;
    const uint32_t MBC = sb + 216360;

    const int tid  = threadIdx.x;
    const int lane = tid & 31;
    const int warp = tid >> 5;
    const int mw   = warp & 3;
    const int nh   = warp >> 2;
    const int blk  = blockIdx.x;

    for (int c = tid; c < 8192; c += 256) {
        const int split = c >> 12;
        const int rr    = (c >> 7) & 31;
        const int seg   = c & 127;
        const long nglob = (long)((rr >> 3) * 1024 + blk * 8 + (rr & 7));
        const __half* srcp = (split ? g_Whh_l : g_Whh_h) + nglob * HID + seg * 8;
        float4 v = *(const float4*)srcp;
        *(float4*)((split ? Ws_l : Ws_h) + rr * 1032 + seg * 8) = v;
    }
    for (int cell = tid; cell < 512; cell += 256) {
        const int b = cell >> 3, u = cell & 7;
        Cs[cell] = c0[b * HID + blk * 8 + u];
    }
    if (tid == 0) {
#pragma unroll
        for (int s = 0; s < 4; s++) MBAR_INIT(MBF + s * 8, 1);
        MBAR_INIT(MBP, 1);
#pragma unroll
        for (int s = 0; s < 4; s++) MBAR_INIT(MBC + s * 8, 8);
    }
    __syncthreads();

    const int q = lane >> 3, r8 = lane & 7;
    const int rowA = (q & 1) * 8 + r8;
    const int colA = (q >> 1) * 8;
    const int rowB = (q >> 1) * 8 + r8;
    const int colB = (q & 1) * 8;
    const int groupRow = lane >> 2;
    const int colPos   = lane & 3;

    const uint32_t aRowByte = (uint32_t)((mw * 16 + rowA) * 128 + colA * 2);
    const int c2 = blk >> 3;

    for (int t = 0; t < 63; t++) {
        const char* hsrc = t ? ((const char*)g_Hb + (size_t)(t - 1) * HB_STEP_BYTES)
                             : (const char*)g_H0b;

        if (tid == 0) {
#pragma unroll
            for (int m = 0; m < 3; m++) {
                const int F = t * 4;
                if (F) MBAR_WAIT(MBC + m * 8, (F - 1) & 1);
                MBAR_EXPECT(MBF + m * 8, HB_CHUNK_BYTES);
                bulkcp(HS + m * 16384, hsrc + (size_t)m * HB_CHUNK_BYTES,
                       HB_CHUNK_BYTES, MBF + m * 8);
            }
            MBAR_EXPECT(MBP, 8192);
            bulkcp(PSA, (const char*)g_pre + ((size_t)t * 128 + blk) * 8192, 8192, MBP);
        }

        float aHH[2][4], aHL[2][4], aLH[2][4];
#pragma unroll
        for (int j = 0; j < 2; j++)
#pragma unroll
            for (int k = 0; k < 4; k++) { aHH[j][k] = 0.f; aHL[j][k] = 0.f; aLH[j][k] = 0.f; }

        for (int c = 0; c < 16; c++) {
            if (tid == 0 && c + 3 < 16) {
                const int m = c + 3;
                const int s = m & 3;
                const int F = t * 4 + (m >> 2);
                if (F) MBAR_WAIT(MBC + s * 8, (F - 1) & 1);
                MBAR_EXPECT(MBF + s * 8, HB_CHUNK_BYTES);
                bulkcp(HS + s * 16384, hsrc + (size_t)m * HB_CHUNK_BYTES,
                       HB_CHUNK_BYTES, MBF + s * 8);
            }
            MBAR_WAIT(MBF + (c & 3) * 8, (c >> 2) & 1);
            __syncwarp();
            const uint32_t hb = HS + (c & 3) * 16384;

#pragma unroll
            for (int k16 = 0; k16 < 4; k16++) {
                uint32_t aH[4], aL[4], bH[2][2], bL[2][2];
                const uint32_t aoff = SWZ(aRowByte + (uint32_t)(k16 * 32));
                ldm4s(aH[0], aH[1], aH[2], aH[3], hb + aoff);
                ldm4s(aL[0], aL[1], aL[2], aL[3], hb + 8192 + aoff);
                ldm4(bH[0][0], bH[0][1], bH[1][0], bH[1][1],
                     Ws_h + (nh * 16 + rowB) * 1032 + c * 64 + k16 * 16 + colB);
                ldm4(bL[0][0], bL[0][1], bL[1][0], bL[1][1],
                     Ws_l + (nh * 16 + rowB) * 1032 + c * 64 + k16 * 16 + colB);
#pragma unroll
                for (int j = 0; j < 2; j++) {
                    mma16816(aHH[j], aH, bH[j]);
                    mma16816(aHL[j], aH, bL[j]);
                    mma16816(aLH[j], aL, bH[j]);
                }
            }
            __syncwarp();
            if (lane == 0) MBAR_ARRIVE(MBC + (c & 3) * 8);
        }

#pragma unroll
        for (int j = 0; j < 2; j++) {
            const int col = nh * 16 + j * 8 + colPos * 2;
            Gs[(mw * 16 + groupRow) * 33 + col]         = aHH[j][0] + aHL[j][0] + aLH[j][0];
            Gs[(mw * 16 + groupRow) * 33 + col + 1]     = aHH[j][1] + aHL[j][1] + aLH[j][1];
            Gs[(mw * 16 + groupRow + 8) * 33 + col]     = aHH[j][2] + aHL[j][2] + aLH[j][2];
            Gs[(mw * 16 + groupRow + 8) * 33 + col + 1] = aHH[j][3] + aHL[j][3] + aLH[j][3];
        }
        __syncthreads();
        MBAR_WAIT(MBP, t & 1);

        char* hdst = (char*)g_Hb + (size_t)t * HB_STEP_BYTES + (size_t)c2 * HB_CHUNK_BYTES;
        for (int cell = tid; cell < 512; cell += 256) {
            const int b = cell >> 3, u = cell & 7;
            const float gi = Gs[b * 33 + u]      * INV_SCALE + Ps[b * 32 + u];
            const float gf = Gs[b * 33 + 8 + u]  * INV_SCALE + Ps[b * 32 + 8 + u];
            const float gg = Gs[b * 33 + 16 + u] * INV_SCALE + Ps[b * 32 + 16 + u];
            const float go = Gs[b * 33 + 24 + u] * INV_SCALE + Ps[b * 32 + 24 + u];

            const float i_ = 1.f / (1.f + expf(-gi));
            const float f_ = 1.f / (1.f + expf(-gf));
            const float g_ = tanhf(gg);
            const float o_ = 1.f / (1.f + expf(-go));

            const float cN = f_ * Cs[cell] + i_ * g_;
            Cs[cell] = cN;
            const float h = o_ * tanhf(cN);

            const float a = h * SCALE_A;
            const __half hh = __float2half_rn(a);
            const __half hl = __float2half_rn(a - __half2float(hh));
            const int inner = (blk & 7) * 8 + u;
            const uint32_t off = SWZ((uint32_t)(b * 128 + inner * 2));
            *(__half*)(hdst + off)        = hh;
            *(__half*)(hdst + 8192 + off) = hl;
        }

        __syncthreads();
        if (tid == 0) {
            asm volatile("fence.proxy.async;" ::: "memory");
            __threadfence();
            atomicAdd(&g_bar, 1u);
            volatile unsigned* p = &g_bar;
            const unsigned target = (unsigned)(t + 1) * NBLK;
            while (*p < target) { __nanosleep(32); }
            __threadfence();
            asm volatile("fence.proxy.async;" ::: "memory");
        }
        __syncthreads();
    }
}

// ---- K3: logits GEMM 128x256, 512 thr, bulkcp producer/consumer pipeline ----
#define LOG_STG   98304
#define LOG_TAIL  196608
#define LOG_SMEM  (LOG_TAIL + 1024 + 512 + 4 * 2048 + 512 + 64)
__global__ __launch_bounds__(512, 1)
void logits_mma_kernel(const float* __restrict__ bout, const int* __restrict__ ot) {
    extern __shared__ __align__(16) char dsm[];
    const uint32_t sb = (uint32_t)__cvta_generic_to_shared(dsm);
    float* bout_s    = (float*)(dsm + LOG_TAIL);
    int*   labels_s  = (int*)(dsm + LOG_TAIL + 1024);
    float* wmax      = (float*)(dsm + LOG_TAIL + 1536);
    int*   warg      = (int*)(dsm + LOG_TAIL + 1536 + 2048);
    float* wsum      = (float*)(dsm + LOG_TAIL + 1536 + 4096);
    float* wlab      = (float*)(dsm + LOG_TAIL + 1536 + 6144);
    float* rowmax_s  = (float*)(dsm + LOG_TAIL + 1536 + 8192);
    const uint32_t MBFL = sb + LOG_TAIL + 1536 + 8192 + 512;
    const uint32_t MBCN = MBFL + 16;

    const int tid  = threadIdx.x;
    const int lane = tid & 31;
    const int warp = tid >> 5;
    const int wm   = warp >> 2;
    const int wn   = warp & 3;
    const int mblk = blockIdx.x * 128;
    const int nblk = blockIdx.y * 256;

    if (tid < 256) bout_s[tid] = bout[nblk + tid];
    if (tid < 128) labels_s[tid] = (mblk + tid < M_ROWS) ? ot[64 + mblk + tid] : -1;
    if (tid == 0) {
        MBAR_INIT(MBFL, 1);     MBAR_INIT(MBFL + 8, 1);
        MBAR_INIT(MBCN, 16);    MBAR_INIT(MBCN + 8, 16);
    }
    __syncthreads();

    int s0 = blockIdx.x * 2;     if (s0 > 62) s0 = 62;
    int s1 = blockIdx.x * 2 + 1; if (s1 > 62) s1 = 62;
    const char* a0 = (const char*)g_Hb + (size_t)s0 * HB_STEP_BYTES;
    const char* a1 = (const char*)g_Hb + (size_t)s1 * HB_STEP_BYTES;
    const char* bb = (const char*)g_Bb + (size_t)(blockIdx.y * 16) * 65536;

    if (tid == 0) {
#pragma unroll
        for (int p = 0; p < 2; p++) {
            const uint32_t stg = sb + p * LOG_STG;
            MBAR_EXPECT(MBFL + p * 8, 98304);
            bulkcp(stg,         a0 + (size_t)p * HB_CHUNK_BYTES, 16384, MBFL + p * 8);
            bulkcp(stg + 16384, a1 + (size_t)p * HB_CHUNK_BYTES, 16384, MBFL + p * 8);
            bulkcp(stg + 32768, bb + (size_t)p * 65536,          65536, MBFL + p * 8);
        }
    }

    const int q = lane >> 3, r8 = lane & 7;
    const int rowA = (q & 1) * 8 + r8;
    const int colA = (q >> 1) * 8;
    const int rowB = (q >> 1) * 8 + r8;
    const int colB = (q & 1) * 8;

    const uint32_t aStageOff  = (uint32_t)((wm >> 1) * 16384);
    const uint32_t aRowByte   = (uint32_t)(((wm & 1) * 32 + rowA) * 128 + colA * 2);
    const uint32_t bRowByteBase = (uint32_t)((wn * 64 + rowB) * 128 + colB * 2);

    float acc[2][8][4];
#pragma unroll
    for (int i = 0; i < 2; i++)
#pragma unroll
        for (int j = 0; j < 8; j++)
#pragma unroll
            for (int k = 0; k < 4; k++) acc[i][j][k] = 0.f;

    for (int c = 0; c < 16; c++) {
        MBAR_WAIT(MBFL + (c & 1) * 8, (c >> 1) & 1);
        __syncwarp();
        const uint32_t stg = sb + (c & 1) * LOG_STG;
        const uint32_t aBaseS = stg + aStageOff;
        const uint32_t bBaseS = stg + 32768;

#pragma unroll
        for (int k16 = 0; k16 < 4; k16++) {
            uint32_t aH[2][4], aL[2][4];
#pragma unroll
            for (int i = 0; i < 2; i++) {
                const uint32_t ao = SWZ(aRowByte + (uint32_t)(i * 16 * 128 + k16 * 32));
                ldm4s(aH[i][0], aH[i][1], aH[i][2], aH[i][3], aBaseS + ao);
                ldm4s(aL[i][0], aL[i][1], aL[i][2], aL[i][3], aBaseS + 8192 + ao);
            }
#pragma unroll
            for (int j2 = 0; j2 < 4; j2++) {
                uint32_t bH[2][2], bL[2][2];
                const uint32_t bo = SWZ(bRowByteBase + (uint32_t)(j2 * 16 * 128 + k16 * 32));
                ldm4s(bH[0][0], bH[0][1], bH[1][0], bH[1][1], bBaseS + bo);
                ldm4s(bL[0][0], bL[0][1], bL[1][0], bL[1][1], bBaseS + 32768 + bo);
#pragma unroll
                for (int i = 0; i < 2; i++)
#pragma unroll
                    for (int jj = 0; jj < 2; jj++) {
                        mma16816(acc[i][j2 * 2 + jj], aH[i], bH[jj]);
                        mma16816(acc[i][j2 * 2 + jj], aH[i], bL[jj]);
                        mma16816(acc[i][j2 * 2 + jj], aL[i], bH[jj]);
                    }
            }
        }
        __syncwarp();
        if (lane == 0) MBAR_ARRIVE(MBCN + (c & 1) * 8);
        if (tid == 0 && c + 2 < 16) {
            MBAR_WAIT(MBCN + (c & 1) * 8, (c >> 1) & 1);
            const uint32_t stg2 = sb + (c & 1) * LOG_STG;
            MBAR_EXPECT(MBFL + (c & 1) * 8, 98304);
            bulkcp(stg2,         a0 + (size_t)(c + 2) * HB_CHUNK_BYTES, 16384, MBFL + (c & 1) * 8);
            bulkcp(stg2 + 16384, a1 + (size_t)(c + 2) * HB_CHUNK_BYTES, 16384, MBFL + (c & 1) * 8);
            bulkcp(stg2 + 32768, bb + (size_t)(c + 2) * 65536,          65536, MBFL + (c & 1) * 8);
        }
    }

    const int groupRow = lane >> 2;
    const int colPos   = lane & 3;

#pragma unroll
    for (int i = 0; i < 2; i++) {
#pragma unroll
        for (int half = 0; half < 2; half++) {
            const int row_local = wm * 32 + i * 16 + groupRow + half * 8;
            const int lbl = labels_s[row_local];
            float mv = -1e30f; int ma = 0x7fffffff; float lv = -1e30f;
#pragma unroll
            for (int j = 0; j < 8; j++) {
#pragma unroll
                for (int kb = 0; kb < 2; kb++) {
                    const int cl = wn * 64 + j * 8 + colPos * 2 + kb;
                    const float v = acc[i][j][half * 2 + kb] * INV_SCALE + bout_s[cl];
                    const int colg = nblk + cl;
                    if (v > mv) { mv = v; ma = colg; }
                    if (colg == lbl) lv = v;
                }
            }
#pragma unroll
            for (int m = 1; m < 4; m <<= 1) {
                const float ov = __shfl_xor_sync(0xffffffffu, mv, m);
                const int   oa = __shfl_xor_sync(0xffffffffu, ma, m);
                const float ol = __shfl_xor_sync(0xffffffffu, lv, m);
                if (ov > mv || (ov == mv && oa < ma)) { mv = ov; ma = oa; }
                lv = fmaxf(lv, ol);
            }
            if (colPos == 0) {
                wmax[row_local * 4 + wn] = mv;
                warg[row_local * 4 + wn] = ma;
                wlab[row_local * 4 + wn] = lv;
            }
        }
    }
    __syncthreads();

    if (tid < 128) {
        float mv = wmax[tid * 4]; int ma = warg[tid * 4]; float lv = wlab[tid * 4];
#pragma unroll
        for (int x = 1; x < 4; x++) {
            const float v = wmax[tid * 4 + x]; const int a = warg[tid * 4 + x];
            if (v > mv || (v == mv && a < ma)) { mv = v; ma = a; }
            lv = fmaxf(lv, wlab[tid * 4 + x]);
        }
        rowmax_s[tid] = mv;
        if (mblk + tid < M_ROWS) {
            const long p = (long)(mblk + tid) * NCHUNK + blockIdx.y;
            g_pmax[p] = mv;
            g_parg[p] = ma;
            g_plab[p] = lv;
        }
    }
    __syncthreads();

#pragma unroll
    for (int i = 0; i < 2; i++) {
#pragma unroll
        for (int half = 0; half < 2; half++) {
            const int row_local = wm * 32 + i * 16 + groupRow + half * 8;
            const float rm = rowmax_s[row_local];
            float s = 0.f;
#pragma unroll
            for (int j = 0; j < 8; j++)
#pragma unroll
                for (int kb = 0; kb < 2; kb++) {
                    const int cl = wn * 64 + j * 8 + colPos * 2 + kb;
                    s += __expf(acc[i][j][half * 2 + kb] * INV_SCALE + bout_s[cl] - rm);
                }
#pragma unroll
            for (int m = 1; m < 4; m <<= 1)
                s += __shfl_xor_sync(0xffffffffu, s, m);
            if (colPos == 0) wsum[row_local * 4 + wn] = s;
        }
    }
    __syncthreads();

    if (tid < 128 && mblk + tid < M_ROWS) {
        float s = wsum[tid * 4] + wsum[tid * 4 + 1] + wsum[tid * 4 + 2] + wsum[tid * 4 + 3];
        g_psum[(long)(mblk + tid) * NCHUNK + blockIdx.y] = s;
    }
}

// ---- K4: per-row cross-chunk reduction ----
__global__ void reduce_rows_kernel(float* __restrict__ out) {
    const int m = blockIdx.x;
    const int tid = threadIdx.x;
    const long base = (long)m * NCHUNK;

    float mv = -1e30f; int ma = 0x7fffffff;
    for (int c = tid; c < NCHUNK; c += 128) {
        const float v = g_pmax[base + c];
        const int   a = g_parg[base + c];
        if (v > mv || (v == mv && a < ma)) { mv = v; ma = a; }
    }
    __shared__ float sv[128]; __shared__ int sa[128];
    sv[tid] = mv; sa[tid] = ma;
    __syncthreads();
    for (int off = 64; off > 0; off >>= 1) {
        if (tid < off) {
            const float v = sv[tid + off]; const int a = sa[tid + off];
            if (v > sv[tid] || (v == sv[tid] && a < sa[tid])) { sv[tid] = v; sa[tid] = a; }
        }
        __syncthreads();
    }
    const float gmax = sv[0];
    const int   garg = sa[0];
    __syncthreads();

    float ssum = 0.f, lab = -1e30f;
    for (int c = tid; c < NCHUNK; c += 128) {
        ssum += g_psum[base + c] * __expf(g_pmax[base + c] - gmax);
        lab = fmaxf(lab, g_plab[base + c]);
    }
    __shared__ float s2[128]; __shared__ float s3[128];
    s2[tid] = ssum; s3[tid] = lab;
    __syncthreads();
    for (int off = 64; off > 0; off >>= 1) {
        if (tid < off) {
            s2[tid] += s2[tid + off];
            s3[tid] = fmaxf(s3[tid], s3[tid + off]);
        }
        __syncthreads();
    }

    if (tid == 0) {
        const float lse = gmax + logf(s2[0]);
        g_nll[m] = lse - s3[0];
        out[65 + m] = (float)garg;
    }
}

// ---- K5: loss assembly + first result row ----
__global__ void finalize_kernel(const int* __restrict__ ot, float* __restrict__ out) {
    const int tid = threadIdx.x;
    __shared__ float ps[64];
    if (tid < 64) out[1 + tid] = 1.0f;
    if (tid < 63) {
        float s = 0.f, cnt = 0.f;
        for (int b = 0; b < 64; b++) {
            const int lbl = ot[(tid + 1) * 64 + b];
            if (lbl != 0) { s += g_nll[tid * 64 + b]; cnt += 1.f; }
        }
        ps[tid] = s / fmaxf(cnt, 1.f);
    }
    __syncthreads();
    if (tid == 0) {
        float loss = 0.f;
        for (int t = 0; t < 63; t++) loss += ps[t];
        out[0] = loss;
    }
}

// ---- entry point ----
extern "C" void kernel_launch(void* const* d_in, const int* in_sizes, int n_in,
                              void* d_out, int out_size) {
    const int*   ot   = (const int*)  d_in[0];
    const float* h0   = (const float*)d_in[3];
    const float* c0   = (const float*)d_in[4];
    const float* emb  = (const float*)d_in[5];
    const float* Wih  = (const float*)d_in[6];
    const float* Whh  = (const float*)d_in[7];
    const float* bih  = (const float*)d_in[8];
    const float* bhh  = (const float*)d_in[9];
    const float* Wout = (const float*)d_in[10];
    const float* bout = (const float*)d_in[11];
    float* out = (float*)d_out;

    cudaFuncSetAttribute(lstm_persistent_kernel,
                         cudaFuncAttributeMaxDynamicSharedMemorySize, LSTM_SMEM);
    cudaFuncSetAttribute(pre_mma_kernel,
                         cudaFuncAttributeMaxDynamicSharedMemorySize, PRE_SMEM);
    cudaFuncSetAttribute(logits_mma_kernel,
                         cudaFuncAttributeMaxDynamicSharedMemorySize, LOG_SMEM);

    prep_all_kernel<<<(VOCAB * HID / 4) / 256, 256>>>(ot, emb, Wih, Whh, h0, Wout);
    pre_mma_kernel<<<dim3(63, 32), 256, PRE_SMEM>>>(bih, bhh);
    lstm_persistent_kernel<<<NBLK, 256, LSTM_SMEM>>>(c0);
    logits_mma_kernel<<<dim3(32, 125), 512, LOG_SMEM>>>(bout, ot);
    reduce_rows_kernel<<<4032, 128>>>(out);
    finalize_kernel<<<1, 64>>>(ot, out);
}